// round 14
// baseline (speedup 1.0000x reference)
#include <cuda_runtime.h>
#include <cuda.h>
#include <cuda_fp16.h>
#include <math.h>
#include <cstdint>

#define NN   20000
#define EE   320000
#define ETOT 340000
#define FIN  384
#define F1   1024
#define HH1  4
#define HD   256
#define F2   256
#define PHID 128
#define NSPLIT 10112          // 79 row tiles of 128; divisible by 4
#define TLO 79
#define THI 78

// ---------------- scratch (static device globals; no runtime alloc) ----------
__device__ float g_yp[NN];
__device__ float g_ss1[NN * HH1];
__device__ float g_sd1[NN * HH1];
__device__ float g_ss2[NN];
__device__ float g_sd2[NN];
__device__ float g_wa[8 * FIN];
__device__ int   g_deg[NN];
__device__ int   g_off[NN + 1];
__device__ int   g_cur[NN];
__device__ int   g_csrc[ETOT];
// fp16 planes (A row-major [M,K]; B transposed [N,K])
__device__ __align__(128) __half g_xh [(size_t)NN * FIN];
__device__ __align__(128) __half g_w1h[(size_t)F1 * FIN];
__device__ __align__(128) __half g_h1h[(size_t)NN * F1];
__device__ __align__(128) __half g_o1h[(size_t)NN * F1];
__device__ __align__(128) __half g_w2h[(size_t)F2 * F1];
__device__ __align__(128) __half g_h2h[(size_t)NN * F2];
__device__ __align__(128) __half g_hh [(size_t)NN * F2];
__device__ __align__(128) __half g_wph[(size_t)PHID * F2];

// ---------------- helpers ----------------
__device__ __forceinline__ uint32_t smem_u32(const void* p) {
    uint32_t a;
    asm("{ .reg .u64 t; cvta.to.shared.u64 t, %1; cvt.u32.u64 %0, t; }" : "=r"(a) : "l"(p));
    return a;
}
__device__ __forceinline__ void ldm4(uint32_t* r, uint32_t a) {
    asm volatile("ldmatrix.sync.aligned.m8n8.x4.shared.b16 {%0,%1,%2,%3}, [%4];"
                 : "=r"(r[0]), "=r"(r[1]), "=r"(r[2]), "=r"(r[3]) : "r"(a));
}
__device__ __forceinline__ void mma16816(float* c, const uint32_t* a, uint32_t b0, uint32_t b1) {
    asm volatile("mma.sync.aligned.m16n8k16.row.col.f32.f16.f16.f32 "
                 "{%0,%1,%2,%3}, {%4,%5,%6,%7}, {%8,%9}, {%0,%1,%2,%3};"
                 : "+f"(c[0]), "+f"(c[1]), "+f"(c[2]), "+f"(c[3])
                 : "r"(a[0]), "r"(a[1]), "r"(a[2]), "r"(a[3]), "r"(b0), "r"(b1));
}
#define MBARRIER_INIT(mb, c) \
    asm volatile("mbarrier.init.shared.b64 [%0], %1;" :: "r"((uint32_t)(mb)), "r"((uint32_t)(c)) : "memory")
#define MBARRIER_EXPECT_TX(mb, b) \
    asm volatile("mbarrier.arrive.expect_tx.shared.b64 _, [%0], %1;" \
                 :: "r"((uint32_t)(mb)), "r"((uint32_t)(b)) : "memory")
#define MBARRIER_WAIT_PARITY(mb, par) do { \
    uint32_t _m = (uint32_t)(mb), _p = (uint32_t)(par), _d; \
    asm volatile("{\n\t.reg .pred p;\n\t" \
        "mbarrier.try_wait.parity.acquire.cta.shared::cta.b64 p, [%1], %2;\n\t" \
        "selp.b32 %0, 1, 0, p;\n\t}" : "=r"(_d) : "r"(_m), "r"(_p) : "memory"); \
    if (!_d) { \
        asm volatile("{\n\t.reg .pred P1;\n\tWL_%=:\n\t" \
            "mbarrier.try_wait.parity.acquire.cta.shared::cta.b64 P1, [%0], %1, 0x989680;\n\t" \
            "@P1 bra.uni WD_%=;\n\tbra.uni WL_%=;\n\tWD_%=:\n\t}" \
            :: "r"(_m), "r"(_p) : "memory"); \
    } } while (0)
__device__ __forceinline__ void tma2d(uint32_t dst, const void* map, int x, int y, uint32_t mb) {
    asm volatile(
        "cp.async.bulk.tensor.2d.shared::cta.global.tile.mbarrier::complete_tx::bytes "
        "[%0], [%1, {%2, %3}], [%4];"
        :: "r"(dst), "l"(map), "r"(x), "r"(y), "r"(mb) : "memory");
}
#define SW128(o) ((o) ^ (((o) >> 3) & 0x70u))
__device__ __forceinline__ float lrelu(float x) { return x > 0.f ? x : 0.2f * x; }

// ---------------- prep kernels ----------------
__global__ void k_cast4(const float4* __restrict__ in, __half2* __restrict__ o, int total4) {
    int i = blockIdx.x * blockDim.x + threadIdx.x;
    if (i >= total4) return;
    float4 v = in[i];
    o[2 * i]     = __floats2half2_rn(v.x, v.y);
    o[2 * i + 1] = __floats2half2_rn(v.z, v.w);
}
__global__ void k_castT(const float* __restrict__ W, __half* __restrict__ o, int K, int N) {
    int i = blockIdx.x * blockDim.x + threadIdx.x;
    if (i >= K * N) return;
    int k = i / N, n = i % N;
    o[(size_t)n * K + k] = __float2half_rn(W[i]);
}
__global__ void k_zeroinit(float* ss2, float* sd2, float* yp, int* deg, int n) {
    int i = blockIdx.x * blockDim.x + threadIdx.x;
    if (i < n) { ss2[i] = 0.f; sd2[i] = 0.f; yp[i] = 0.f; deg[i] = 1; }
}
// wa[j][k] = sum_c W1[k, h*256+c] * a[h][c], j = h*2 + {src,dst}
__global__ void k_wa1(const float* __restrict__ W1, const float* __restrict__ as1,
                      const float* __restrict__ ad1, float* __restrict__ wa) {
    int i = blockIdx.x * blockDim.x + threadIdx.x;
    if (i >= 8 * FIN) return;
    int j = i / FIN, k = i % FIN;
    int h = j >> 1;
    const float* av = (j & 1) ? ad1 : as1;
    float s = 0.f;
    for (int c = 0; c < HD; c++) s += W1[(size_t)k * F1 + h * HD + c] * av[h * HD + c];
    wa[(size_t)j * FIN + k] = s;
}
// ss1/sd1 = x @ wa^T  (warp per node)
__global__ void k_slogits_x(const float* __restrict__ x, const float* __restrict__ wa,
                            float* __restrict__ ss, float* __restrict__ sd) {
    int w = (blockIdx.x * blockDim.x + threadIdx.x) >> 5;
    int lane = threadIdx.x & 31;
    if (w >= NN) return;
    float s[8] = {0, 0, 0, 0, 0, 0, 0, 0};
    const float* row = x + (size_t)w * FIN;
    for (int k = lane; k < FIN; k += 32) {
        float xv = row[k];
#pragma unroll
        for (int j = 0; j < 8; j++) s[j] += xv * wa[j * FIN + k];
    }
#pragma unroll
    for (int j = 0; j < 8; j++)
#pragma unroll
        for (int o = 16; o; o >>= 1) s[j] += __shfl_xor_sync(0xffffffffu, s[j], o);
    if (lane == 0) {
#pragma unroll
        for (int h = 0; h < 4; h++) { ss[w * 4 + h] = s[2 * h]; sd[w * 4 + h] = s[2 * h + 1]; }
    }
}

// ============== TMA HMMA GEMM: C[M,N] = A[M,K] @ B[N,K]^T ====================
#define TG_STAGE 32768
#define TG_SMEM (1024 + 3 * TG_STAGE)

__global__ void __launch_bounds__(256, 2)
hgemm_tma(const __grid_constant__ CUtensorMap mA,
          const __grid_constant__ CUtensorMap mB,
          float* __restrict__ C, __half* __restrict__ Ch, int M, int N, int K, int ytile0,
          float* __restrict__ ss, float* __restrict__ sd,
          const float* __restrict__ av, const float* __restrict__ bv,
          float* __restrict__ yp, const float* __restrict__ bp1,
          const float* __restrict__ wp2) {
    extern __shared__ unsigned char smraw[];
    const uint32_t base0 = (smem_u32(smraw) + 1023u) & ~1023u;
    const uint32_t mbb = base0;
    const uint32_t tile0 = base0 + 1024;
    const int tid = threadIdx.x, wid = tid >> 5, lane = tid & 31;
    const int bm = (blockIdx.y + ytile0) * 128, bn = blockIdx.x * 128;
    const int wr = (wid >> 1) * 32, wn = (wid & 1) * 64;
    const int nc = K >> 6;

    if (tid == 0) {
        MBARRIER_INIT(mbb + 0, 1);
        MBARRIER_INIT(mbb + 8, 1);
        MBARRIER_INIT(mbb + 16, 1);
    }
    __syncthreads();

    if (tid == 0) {
#pragma unroll
        for (int s = 0; s < 2; s++) {
            uint32_t mb = mbb + 8u * s;
            uint32_t t = tile0 + (uint32_t)s * TG_STAGE;
            MBARRIER_EXPECT_TX(mb, TG_STAGE);
            tma2d(t,          &mA, s * 64, bm, mb);
            tma2d(t + 16384u, &mB, s * 64, bn, mb);
        }
    }

    float acc[2][8][4];
#pragma unroll
    for (int a = 0; a < 2; a++)
#pragma unroll
        for (int b = 0; b < 8; b++)
#pragma unroll
            for (int c = 0; c < 4; c++) acc[a][b][c] = 0.f;

    for (int i = 0; i < nc; i++) {
        const int b = i % 3;
        MBARRIER_WAIT_PARITY(mbb + 8u * b, (i / 3) & 1);
        __syncthreads();
        if (tid == 0 && i + 2 < nc) {
            const int nb = (i + 2) % 3;
            uint32_t mb = mbb + 8u * nb;
            uint32_t t = tile0 + (uint32_t)nb * TG_STAGE;
            MBARRIER_EXPECT_TX(mb, TG_STAGE);
            tma2d(t,          &mA, (i + 2) * 64, bm, mb);
            tma2d(t + 16384u, &mB, (i + 2) * 64, bn, mb);
        }

        const uint32_t tA = tile0 + (uint32_t)b * TG_STAGE;
        const uint32_t tB = tA + 16384u;
        const int gq = lane >> 3;
#pragma unroll
        for (int ks = 0; ks < 4; ks++) {
            uint32_t ar[2][4], br[4][4];
#pragma unroll
            for (int mt = 0; mt < 2; mt++) {
                uint32_t lin = (uint32_t)(wr + mt * 16 + (lane & 15)) * 128u
                             + (uint32_t)(ks * 32 + (lane >> 4) * 16);
                ldm4(ar[mt], tA + SW128(lin));
            }
#pragma unroll
            for (int bt = 0; bt < 4; bt++) {
                uint32_t lin = (uint32_t)(wn + bt * 16 + ((gq >> 1) << 3) + (lane & 7)) * 128u
                             + (uint32_t)(ks * 32 + (gq & 1) * 16);
                ldm4(br[bt], tB + SW128(lin));
            }
#pragma unroll
            for (int mt = 0; mt < 2; mt++)
#pragma unroll
                for (int j = 0; j < 8; j++) {
                    const int bt = j >> 1, p0 = (j & 1) * 2;
                    mma16816(acc[mt][j], ar[mt], br[bt][p0], br[bt][p0 + 1]);
                }
        }
    }

    // epilogue: fp32 and/or fp16 stores
#pragma unroll
    for (int mt = 0; mt < 2; mt++) {
        int m0 = bm + wr + mt * 16 + (lane >> 2);
#pragma unroll
        for (int j = 0; j < 8; j++) {
            int n0 = bn + wn + j * 8 + (lane & 3) * 2;
            if (C) {
                if (m0 < M)
                    *(float2*)&C[(size_t)m0 * N + n0] = make_float2(acc[mt][j][0], acc[mt][j][1]);
                if (m0 + 8 < M)
                    *(float2*)&C[(size_t)(m0 + 8) * N + n0] = make_float2(acc[mt][j][2], acc[mt][j][3]);
            }
            if (Ch) {
                if (m0 < M)
                    *(__half2*)&Ch[(size_t)m0 * N + n0] =
                        __floats2half2_rn(acc[mt][j][0], acc[mt][j][1]);
                if (m0 + 8 < M)
                    *(__half2*)&Ch[(size_t)(m0 + 8) * N + n0] =
                        __floats2half2_rn(acc[mt][j][2], acc[mt][j][3]);
            }
        }
    }

    // fused attention-logit partials
    if (ss) {
        const int Hh = N >> 8;
        const int h = bn >> 8;
        const int cb0 = (bn & 255) + wn + (lane & 3) * 2;
#pragma unroll
        for (int mt = 0; mt < 2; mt++) {
            int m0 = bm + wr + mt * 16 + (lane >> 2);
            float ps0 = 0.f, pd0 = 0.f, ps1 = 0.f, pd1 = 0.f;
#pragma unroll
            for (int j = 0; j < 8; j++) {
                int cb = cb0 + j * 8;
                float a0 = av[h * 256 + cb], a1 = av[h * 256 + cb + 1];
                float d0 = bv[h * 256 + cb], d1 = bv[h * 256 + cb + 1];
                ps0 += acc[mt][j][0] * a0 + acc[mt][j][1] * a1;
                pd0 += acc[mt][j][0] * d0 + acc[mt][j][1] * d1;
                ps1 += acc[mt][j][2] * a0 + acc[mt][j][3] * a1;
                pd1 += acc[mt][j][2] * d0 + acc[mt][j][3] * d1;
            }
#pragma unroll
            for (int o = 1; o < 4; o <<= 1) {
                ps0 += __shfl_xor_sync(0xffffffffu, ps0, o);
                pd0 += __shfl_xor_sync(0xffffffffu, pd0, o);
                ps1 += __shfl_xor_sync(0xffffffffu, ps1, o);
                pd1 += __shfl_xor_sync(0xffffffffu, pd1, o);
            }
            if ((lane & 3) == 0) {
                if (m0 < M) {
                    atomicAdd(&ss[m0 * Hh + h], ps0);
                    atomicAdd(&sd[m0 * Hh + h], pd0);
                }
                if (m0 + 8 < M) {
                    atomicAdd(&ss[(m0 + 8) * Hh + h], ps1);
                    atomicAdd(&sd[(m0 + 8) * Hh + h], pd1);
                }
            }
        }
    }

    // fused influence partial (N == 128)
    if (yp) {
#pragma unroll
        for (int mt = 0; mt < 2; mt++) {
            int m0 = bm + wr + mt * 16 + (lane >> 2);
            float p0 = 0.f, p1 = 0.f;
#pragma unroll
            for (int j = 0; j < 8; j++) {
                int n0 = wn + j * 8 + (lane & 3) * 2;
                float w0 = wp2[n0], w1 = wp2[n0 + 1];
                float b0 = bp1[n0], b1e = bp1[n0 + 1];
                p0 += fmaxf(acc[mt][j][0] + b0, 0.f) * w0 + fmaxf(acc[mt][j][1] + b1e, 0.f) * w1;
                p1 += fmaxf(acc[mt][j][2] + b0, 0.f) * w0 + fmaxf(acc[mt][j][3] + b1e, 0.f) * w1;
            }
#pragma unroll
            for (int o = 1; o < 4; o <<= 1) {
                p0 += __shfl_xor_sync(0xffffffffu, p0, o);
                p1 += __shfl_xor_sync(0xffffffffu, p1, o);
            }
            if ((lane & 3) == 0) {
                if (m0 < M) atomicAdd(&yp[m0], p0);
                if (m0 + 8 < M) atomicAdd(&yp[m0 + 8], p1);
            }
        }
    }
}

// ---------------- CSR build ----------------
__global__ void k_deg_count(const int* __restrict__ dst, int e) {
    int i = blockIdx.x * blockDim.x + threadIdx.x;
    if (i < e) atomicAdd(&g_deg[dst[i]], 1);
}
__global__ void k_scan(int n) {
    __shared__ int sums[1024];
    int tid = threadIdx.x;
    int chunk = (n + 1023) / 1024;
    int lo = tid * chunk, hi = min(lo + chunk, n);
    int s = 0;
    for (int i = lo; i < hi; i++) s += g_deg[i];
    sums[tid] = s;
    __syncthreads();
    for (int d = 1; d < 1024; d <<= 1) {
        int v = (tid >= d) ? sums[tid - d] : 0;
        __syncthreads();
        sums[tid] += v;
        __syncthreads();
    }
    int base = (tid == 0) ? 0 : sums[tid - 1];
    for (int i = lo; i < hi; i++) {
        g_off[i] = base;
        g_cur[i] = base;
        base += g_deg[i];
    }
    if (tid == 1023) g_off[n] = sums[1023];
}
__global__ void k_fill(const int* __restrict__ src, const int* __restrict__ dst, int e, int n) {
    int i = blockIdx.x * blockDim.x + threadIdx.x;
    if (i >= e + n) return;
    int s, d;
    if (i < e) { s = src[i]; d = dst[i]; }
    else       { s = i - e;  d = i - e; }
    int pos = atomicAdd(&g_cur[d], 1);
    g_csrc[pos] = s;
}

// ---------------- grouped per-dst softmax + aggregation ----------------
__device__ __forceinline__ void acc8(float* a, uint4 v, float w) {
    float2 f;
    f = __half22float2(*(__half2*)&v.x); a[0] += f.x * w; a[1] += f.y * w;
    f = __half22float2(*(__half2*)&v.y); a[2] += f.x * w; a[3] += f.y * w;
    f = __half22float2(*(__half2*)&v.z); a[4] += f.x * w; a[5] += f.y * w;
    f = __half22float2(*(__half2*)&v.w); a[6] += f.x * w; a[7] += f.y * w;
}
__device__ __forceinline__ void acc4(float* a, uint2 v, float w) {
    float2 f;
    f = __half22float2(*(__half2*)&v.x); a[0] += f.x * w; a[1] += f.y * w;
    f = __half22float2(*(__half2*)&v.y); a[2] += f.x * w; a[3] += f.y * w;
}

template <int H, int C, int GSZ>
__global__ void __launch_bounds__(256)
k_agg(const __half* __restrict__ feat, const float* __restrict__ ss,
      const float* __restrict__ sd, const float* __restrict__ bias,
      float* __restrict__ out, __half* __restrict__ oh, int d0) {
    constexpr int NG  = 256 / GSZ;
    constexpr int CAP = 64;
    constexpr int HC  = H * C;
    constexpr int PH  = HC / GSZ;
    const int t = threadIdx.x;
    const int g = t / GSZ, gt = t % GSZ;
    const int gw = gt >> 5, lane = gt & 31;
    const int d = d0 + blockIdx.x * NG + g;
    const int base = g_off[d], deg = g_off[d + 1] - base;
    const int capped = min(deg, CAP);
    const int barid = g + 1;

    __shared__ float s_e[NG][CAP * H];
    __shared__ int   s_idx[NG][CAP];
    __shared__ float s_m[NG][H], s_inv[NG][H];

#define GBAR() asm volatile("bar.sync %0, %1;" :: "r"(barid), "r"((int)GSZ) : "memory")

    {
        const int jj = (H == 1) ? gt : (gt >> 2);
        const int h  = (H == 1) ? 0 : (gt & 3);
        const float sdv = sd[d * H + h];
        for (int j0 = 0; j0 < capped; j0 += GSZ / H) {
            int j = j0 + jj;
            if (j < capped) {
                int s = g_csrc[base + j];
                if (h == 0) s_idx[g][j] = s;
                s_e[g][j * H + h] = lrelu(ss[s * H + h] + sdv);
            }
        }
    }
    GBAR();

    if (gw < H) {
        const int h = gw;
        const float sdv = sd[d * H + h];
        float mx = -1e30f;
        for (int j = lane; j < capped; j += 32) mx = fmaxf(mx, s_e[g][j * H + h]);
        for (int j = CAP + lane; j < deg; j += 32) {
            int s = g_csrc[base + j];
            mx = fmaxf(mx, lrelu(ss[s * H + h] + sdv));
        }
#pragma unroll
        for (int o = 16; o; o >>= 1) mx = fmaxf(mx, __shfl_xor_sync(0xffffffffu, mx, o));
        float sm = 0.f;
        for (int j = lane; j < capped; j += 32) sm += expf(s_e[g][j * H + h] - mx);
        for (int j = CAP + lane; j < deg; j += 32) {
            int s = g_csrc[base + j];
            sm += expf(lrelu(ss[s * H + h] + sdv) - mx);
        }
#pragma unroll
        for (int o = 16; o; o >>= 1) sm += __shfl_xor_sync(0xffffffffu, sm, o);
        if (lane == 0) { s_m[g][h] = mx; s_inv[g][h] = 1.f / (sm + 1e-16f); }
    }
    GBAR();

    {
        const int jj = (H == 1) ? gt : (gt >> 2);
        const int h  = (H == 1) ? 0 : (gt & 3);
        const float mh = s_m[g][h], iv = s_inv[g][h];
        for (int j0 = 0; j0 < capped; j0 += GSZ / H) {
            int j = j0 + jj;
            if (j < capped) s_e[g][j * H + h] = expf(s_e[g][j * H + h] - mh) * iv;
        }
    }
    GBAR();

    const int hh = (gt * PH) / C;
    float acc[PH];
#pragma unroll
    for (int k = 0; k < PH; k++) acc[k] = 0.f;
    const float* we = &s_e[g][0];
    const int* sidx = &s_idx[g][0];

    if (PH == 8) {
        const __half* fb = feat + gt * 8;
        uint4 b0 = make_uint4(0, 0, 0, 0), b1 = b0, b2 = b0, b3 = b0;
        if (capped > 0) b0 = *(const uint4*)(fb + (size_t)sidx[0] * HC);
        if (capped > 1) b1 = *(const uint4*)(fb + (size_t)sidx[1] * HC);
        if (capped > 2) b2 = *(const uint4*)(fb + (size_t)sidx[2] * HC);
        if (capped > 3) b3 = *(const uint4*)(fb + (size_t)sidx[3] * HC);
        int j = 0;
        for (; j + 4 <= capped; j += 4) {
            float w0 = we[(j + 0) * H + hh], w1 = we[(j + 1) * H + hh];
            float w2 = we[(j + 2) * H + hh], w3 = we[(j + 3) * H + hh];
            uint4 v0 = b0, v1 = b1, v2 = b2, v3 = b3;
            if (j + 4 < capped) b0 = *(const uint4*)(fb + (size_t)sidx[j + 4] * HC);
            if (j + 5 < capped) b1 = *(const uint4*)(fb + (size_t)sidx[j + 5] * HC);
            if (j + 6 < capped) b2 = *(const uint4*)(fb + (size_t)sidx[j + 6] * HC);
            if (j + 7 < capped) b3 = *(const uint4*)(fb + (size_t)sidx[j + 7] * HC);
            acc8(acc, v0, w0); acc8(acc, v1, w1); acc8(acc, v2, w2); acc8(acc, v3, w3);
        }
        if (j     < capped) acc8(acc, b0, we[(j + 0) * H + hh]);
        if (j + 1 < capped) acc8(acc, b1, we[(j + 1) * H + hh]);
        if (j + 2 < capped) acc8(acc, b2, we[(j + 2) * H + hh]);
    } else {
        const __half* fb = feat + gt * 4;
        uint2 b0 = make_uint2(0, 0), b1 = b0, b2 = b0, b3 = b0;
        if (capped > 0) b0 = *(const uint2*)(fb + (size_t)sidx[0] * HC);
        if (capped > 1) b1 = *(const uint2*)(fb + (size_t)sidx[1] * HC);
        if (capped > 2) b2 = *(const uint2*)(fb + (size_t)sidx[2] * HC);
        if (capped > 3) b3 = *(const uint2*)(fb + (size_t)sidx[3] * HC);
        int j = 0;
        for (; j + 4 <= capped; j += 4) {
            float w0 = we[(j + 0) * H + hh], w1 = we[(j + 1) * H + hh];
            float w2 = we[(j + 2) * H + hh], w3 = we[(j + 3) * H + hh];
            uint2 v0 = b0, v1 = b1, v2 = b2, v3 = b3;
            if (j + 4 < capped) b0 = *(const uint2*)(fb + (size_t)sidx[j + 4] * HC);
            if (j + 5 < capped) b1 = *(const uint2*)(fb + (size_t)sidx[j + 5] * HC);
            if (j + 6 < capped) b2 = *(const uint2*)(fb + (size_t)sidx[j + 6] * HC);
            if (j + 7 < capped) b3 = *(const uint2*)(fb + (size_t)sidx[j + 7] * HC);
            acc4(acc, v0, w0); acc4(acc, v1, w1); acc4(acc, v2, w2); acc4(acc, v3, w3);
        }
        if (j     < capped) acc4(acc, b0, we[(j + 0) * H + hh]);
        if (j + 1 < capped) acc4(acc, b1, we[(j + 1) * H + hh]);
        if (j + 2 < capped) acc4(acc, b2, we[(j + 2) * H + hh]);
    }

    if (deg > CAP) {
        const float mh = s_m[g][hh], iv = s_inv[g][hh];
        const float sdv = sd[d * H + hh];
        for (int j = CAP; j < deg; j++) {
            int s = g_csrc[base + j];
            float w = expf(lrelu(ss[s * H + hh] + sdv) - mh) * iv;
            if (PH == 8) acc8(acc, *(const uint4*)(feat + (size_t)s * HC + gt * 8), w);
            else         acc4(acc, *(const uint2*)(feat + (size_t)s * HC + gt * 4), w);
        }
    }

    const int c0 = gt * PH;
    float vv[PH];
#pragma unroll
    for (int k = 0; k < PH; k++) {
        float v = acc[k] + bias[c0 + k];
        vv[k] = v > 0.f ? v : expm1f(v);
    }
    if (out) {
#pragma unroll
        for (int k = 0; k < PH; k += 2)
            *(float2*)&out[(size_t)d * HC + c0 + k] = make_float2(vv[k], vv[k + 1]);
    }
#pragma unroll
    for (int k = 0; k < PH; k += 2)
        *(__half2*)&oh[(size_t)d * HC + c0 + k] = __floats2half2_rn(vv[k], vv[k + 1]);
#undef GBAR
}

// ---------------- graph mean + sigmoid ----------------
__global__ void k_zero_gf(float* gf) { gf[threadIdx.x] = 0.f; }
__global__ void k_colsum(const float* __restrict__ h, float* __restrict__ gf) {
    float acc = 0.f;
    int t = threadIdx.x;
    for (int r = blockIdx.x; r < NN; r += gridDim.x) acc += h[(size_t)r * F2 + t];
    atomicAdd(&gf[t], acc);
}
__global__ void k_scale_gf(float* gf) { gf[threadIdx.x] *= (1.0f / (float)NN); }
__global__ void k_sigmoid(const float* __restrict__ yp, const float* __restrict__ bp2,
                          float* __restrict__ infl, int n, int i0) {
    int i = blockIdx.x * blockDim.x + threadIdx.x;
    if (i < n) infl[i0 + i] = 1.f / (1.f + expf(-(yp[i0 + i] + bp2[0])));
}

// ---------------- host: tensor-map builder ----------------
typedef CUresult (*PFN_encodeTiled)(
    CUtensorMap*, CUtensorMapDataType, cuuint32_t, void*,
    const cuuint64_t*, const cuuint64_t*, const cuuint32_t*, const cuuint32_t*,
    CUtensorMapInterleave, CUtensorMapSwizzle, CUtensorMapL2promotion,
    CUtensorMapFloatOOBfill);

static CUtensorMap make_map(PFN_encodeTiled enc, void* base, int K, int rows) {
    CUtensorMap m;
    cuuint64_t dims[2]    = {(cuuint64_t)K, (cuuint64_t)rows};
    cuuint64_t strides[1] = {(cuuint64_t)K * 2};
    cuuint32_t box[2]     = {64, 128};
    cuuint32_t es[2]      = {1, 1};
    enc(&m, CU_TENSOR_MAP_DATA_TYPE_FLOAT16, 2, base, dims, strides, box, es,
        CU_TENSOR_MAP_INTERLEAVE_NONE, CU_TENSOR_MAP_SWIZZLE_128B,
        CU_TENSOR_MAP_L2_PROMOTION_L2_128B, CU_TENSOR_MAP_FLOAT_OOB_FILL_NONE);
    return m;
}

// ---------------- launch ----------------
extern "C" void kernel_launch(void* const* d_in, const int* in_sizes, int n_in,
                              void* d_out, int out_size) {
    const float* x   = (const float*)d_in[0];
    const int*   eidx = (const int*)d_in[1];
    const float* W1  = (const float*)d_in[2];
    const float* as1 = (const float*)d_in[3];
    const float* ad1 = (const float*)d_in[4];
    const float* b1  = (const float*)d_in[5];
    const float* W2  = (const float*)d_in[6];
    const float* as2 = (const float*)d_in[7];
    const float* ad2 = (const float*)d_in[8];
    const float* b2  = (const float*)d_in[9];
    const float* Wp1 = (const float*)d_in[10];
    const float* bp1 = (const float*)d_in[11];
    const float* Wp2 = (const float*)d_in[12];
    const float* bp2 = (const float*)d_in[13];

    const int* src = eidx;
    const int* dst = eidx + EE;

    float* out   = (float*)d_out;
    float* out_h = out;
    float* out_g = out + (size_t)NN * F2;
    float* out_i = out_g + F2;

    float *p_yp, *p_ss1, *p_sd1, *p_ss2, *p_sd2, *p_wa;
    int* p_deg;
    __half *p_xh, *p_w1h, *p_h1h, *p_o1h, *p_w2h, *p_h2h, *p_hh, *p_wph;
    cudaGetSymbolAddress((void**)&p_yp, g_yp);
    cudaGetSymbolAddress((void**)&p_ss1, g_ss1);
    cudaGetSymbolAddress((void**)&p_sd1, g_sd1);
    cudaGetSymbolAddress((void**)&p_ss2, g_ss2);
    cudaGetSymbolAddress((void**)&p_sd2, g_sd2);
    cudaGetSymbolAddress((void**)&p_wa,  g_wa);
    cudaGetSymbolAddress((void**)&p_deg, g_deg);
    cudaGetSymbolAddress((void**)&p_xh,  g_xh);
    cudaGetSymbolAddress((void**)&p_w1h, g_w1h);
    cudaGetSymbolAddress((void**)&p_h1h, g_h1h);
    cudaGetSymbolAddress((void**)&p_o1h, g_o1h);
    cudaGetSymbolAddress((void**)&p_w2h, g_w2h);
    cudaGetSymbolAddress((void**)&p_h2h, g_h2h);
    cudaGetSymbolAddress((void**)&p_hh,  g_hh);
    cudaGetSymbolAddress((void**)&p_wph, g_wph);

    PFN_encodeTiled enc = nullptr;
    cudaGetDriverEntryPoint("cuTensorMapEncodeTiled", (void**)&enc, cudaEnableDefault);

    CUtensorMap mA1 = make_map(enc, p_xh,  FIN, NN);
    CUtensorMap mB1 = make_map(enc, p_w1h, FIN, F1);
    CUtensorMap mA2 = make_map(enc, p_o1h, F1,  NN);
    CUtensorMap mB2 = make_map(enc, p_w2h, F1,  F2);
    CUtensorMap mA3 = make_map(enc, p_hh,  F2,  NN);
    CUtensorMap mB3 = make_map(enc, p_wph, F2, PHID);

    cudaFuncSetAttribute(hgemm_tma, cudaFuncAttributeMaxDynamicSharedMemorySize, TG_SMEM);

    static cudaStream_t s1 = nullptr;
    static cudaEvent_t evF1 = nullptr, evW1 = nullptr, evJ1 = nullptr, evA1lo = nullptr,
                       evS1a = nullptr, evA2lo = nullptr, evA2hi = nullptr, evJ2 = nullptr;
    if (!s1) {
        cudaStreamCreateWithFlags(&s1, cudaStreamNonBlocking);
        cudaEventCreateWithFlags(&evF1,  cudaEventDisableTiming);
        cudaEventCreateWithFlags(&evW1,  cudaEventDisableTiming);
        cudaEventCreateWithFlags(&evJ1,  cudaEventDisableTiming);
        cudaEventCreateWithFlags(&evA1lo, cudaEventDisableTiming);
        cudaEventCreateWithFlags(&evS1a, cudaEventDisableTiming);
        cudaEventCreateWithFlags(&evA2lo, cudaEventDisableTiming);
        cudaEventCreateWithFlags(&evA2hi, cudaEventDisableTiming);
        cudaEventCreateWithFlags(&evJ2,  cudaEventDisableTiming);
    }

    // ---- side fork: W1 cast -> evW1, then logits-from-x, zeros, casts, CSR ----
    cudaEventRecord(evF1, 0);
    cudaStreamWaitEvent(s1, evF1, 0);
    k_castT<<<(FIN * F1 + 255) / 256, 256, 0, s1>>>(W1, p_w1h, FIN, F1);
    cudaEventRecord(evW1, s1);
    k_wa1<<<(8 * FIN + 255) / 256, 256, 0, s1>>>(W1, as1, ad1, p_wa);
    k_slogits_x<<<(NN * 32 + 255) / 256, 256, 0, s1>>>(x, p_wa, p_ss1, p_sd1);
    k_zeroinit<<<(NN + 255) / 256, 256, 0, s1>>>(p_ss2, p_sd2, p_yp, p_deg, NN);
    k_castT<<<(F1 * F2 + 255) / 256, 256, 0, s1>>>(W2, p_w2h, F1, F2);
    k_castT<<<(F2 * PHID + 255) / 256, 256, 0, s1>>>(Wp1, p_wph, F2, PHID);
    k_deg_count<<<(EE + 255) / 256, 256, 0, s1>>>(dst, EE);
    k_scan<<<1, 1024, 0, s1>>>(NN);
    k_fill<<<(ETOT + 255) / 256, 256, 0, s1>>>(src, dst, EE, NN);
    cudaEventRecord(evJ1, s1);

    // ---- main: cast x (vectorized) -> GEMM1 (fp16 out, no fused logits) ----
    k_cast4<<<(NN * FIN / 4 + 255) / 256, 256>>>((const float4*)x, (__half2*)p_xh, NN * FIN / 4);
    cudaStreamWaitEvent(0, evW1, 0);
    hgemm_tma<<<dim3(F1 / 128, TLO + THI), 256, TG_SMEM>>>(mA1, mB1, nullptr, p_h1h,
                                                           NN, F1, FIN, 0,
                                                           nullptr, nullptr, nullptr, nullptr,
                                                           nullptr, nullptr, nullptr);
    cudaStreamWaitEvent(0, evJ1, 0);

    // ---- agg1 split-pipeline with GEMM2 (fp16 out + fused ss2/sd2) ----
    k_agg<HH1, HD, 128><<<NSPLIT / 2, 256>>>(p_h1h, p_ss1, p_sd1, b1, nullptr, p_o1h, 0);
    cudaEventRecord(evA1lo, 0);
    cudaStreamWaitEvent(s1, evA1lo, 0);
    hgemm_tma<<<dim3(F2 / 128, TLO), 256, TG_SMEM, s1>>>(mA2, mB2, nullptr, p_h2h,
                                                         NN, F2, F1, 0,
                                                         p_ss2, p_sd2, as2, ad2,
                                                         nullptr, nullptr, nullptr);
    cudaEventRecord(evS1a, s1);

    k_agg<HH1, HD, 128><<<(NN - NSPLIT) / 2, 256>>>(p_h1h, p_ss1, p_sd1, b1, nullptr, p_o1h, NSPLIT);
    hgemm_tma<<<dim3(F2 / 128, THI), 256, TG_SMEM>>>(mA2, mB2, nullptr, p_h2h,
                                                     NN, F2, F1, TLO,
                                                     p_ss2, p_sd2, as2, ad2,
                                                     nullptr, nullptr, nullptr);
    cudaStreamWaitEvent(0, evS1a, 0);

    // ---- agg2 split-pipeline with GEMM3 (fused influence partial) ----
    k_agg<1, F2, 64><<<NSPLIT / 4, 256>>>(p_h2h, p_ss2, p_sd2, b2, out_h, p_hh, 0);
    cudaEventRecord(evA2lo, 0);
    cudaStreamWaitEvent(s1, evA2lo, 0);
    hgemm_tma<<<dim3(1, TLO), 256, TG_SMEM, s1>>>(mA3, mB3, nullptr, nullptr,
                                                  NN, PHID, F2, 0,
                                                  nullptr, nullptr, nullptr, nullptr,
                                                  p_yp, bp1, Wp2);
    k_sigmoid<<<(NSPLIT + 255) / 256, 256, 0, s1>>>(p_yp, bp2, out_i, NSPLIT, 0);

    k_agg<1, F2, 64><<<(NN - NSPLIT) / 4, 256>>>(p_h2h, p_ss2, p_sd2, b2, out_h, p_hh, NSPLIT);
    cudaEventRecord(evA2hi, 0);

    // side: graph mean (needs full out_h)
    cudaStreamWaitEvent(s1, evA2hi, 0);
    k_zero_gf<<<1, F2, 0, s1>>>(out_g);
    k_colsum<<<160, F2, 0, s1>>>(out_h, out_g);
    k_scale_gf<<<1, F2, 0, s1>>>(out_g);
    cudaEventRecord(evJ2, s1);

    // main: GEMM3_hi (fused influence) + sigmoid_hi
    hgemm_tma<<<dim3(1, THI), 256, TG_SMEM>>>(mA3, mB3, nullptr, nullptr,
                                              NN, PHID, F2, TLO,
                                              nullptr, nullptr, nullptr, nullptr,
                                              p_yp, bp1, Wp2);
    k_sigmoid<<<(NN - NSPLIT + 255) / 256, 256>>>(p_yp, bp2, out_i, NN - NSPLIT, NSPLIT);
    cudaStreamWaitEvent(0, evJ2, 0);
}

// round 15
// speedup vs baseline: 1.1517x; 1.1517x over previous
#include <cuda_runtime.h>
#include <cuda.h>
#include <cuda_fp16.h>
#include <math.h>
#include <cstdint>

#define NN   20000
#define EE   320000
#define ETOT 340000
#define FIN  384
#define F1   1024
#define HH1  4
#define HD   256
#define F2   256
#define PHID 128
#define NSPLIT 10112          // 79 row tiles of 128; divisible by 4
#define TLO 79
#define THI 78

// ---------------- scratch (static device globals; no runtime alloc) ----------
__device__ float g_yp[NN];            // influence partial (atomic accum)
__device__ float g_ss1[NN * HH1];
__device__ float g_sd1[NN * HH1];
__device__ float g_ss2[NN];
__device__ float g_sd2[NN];
__device__ int   g_deg[NN];
__device__ int   g_off[NN + 1];
__device__ int   g_cur[NN];
__device__ int   g_csrc[ETOT];
// fp16 planes (A row-major [M,K]; B transposed [N,K])
__device__ __align__(128) __half g_xh [(size_t)NN * FIN];
__device__ __align__(128) __half g_w1h[(size_t)F1 * FIN];
__device__ __align__(128) __half g_h1h[(size_t)NN * F1];
__device__ __align__(128) __half g_o1h[(size_t)NN * F1];
__device__ __align__(128) __half g_w2h[(size_t)F2 * F1];
__device__ __align__(128) __half g_h2h[(size_t)NN * F2];
__device__ __align__(128) __half g_hh [(size_t)NN * F2];
__device__ __align__(128) __half g_wph[(size_t)PHID * F2];

// ---------------- helpers ----------------
__device__ __forceinline__ uint32_t smem_u32(const void* p) {
    uint32_t a;
    asm("{ .reg .u64 t; cvta.to.shared.u64 t, %1; cvt.u32.u64 %0, t; }" : "=r"(a) : "l"(p));
    return a;
}
__device__ __forceinline__ void ldm4(uint32_t* r, uint32_t a) {
    asm volatile("ldmatrix.sync.aligned.m8n8.x4.shared.b16 {%0,%1,%2,%3}, [%4];"
                 : "=r"(r[0]), "=r"(r[1]), "=r"(r[2]), "=r"(r[3]) : "r"(a));
}
__device__ __forceinline__ void mma16816(float* c, const uint32_t* a, uint32_t b0, uint32_t b1) {
    asm volatile("mma.sync.aligned.m16n8k16.row.col.f32.f16.f16.f32 "
                 "{%0,%1,%2,%3}, {%4,%5,%6,%7}, {%8,%9}, {%0,%1,%2,%3};"
                 : "+f"(c[0]), "+f"(c[1]), "+f"(c[2]), "+f"(c[3])
                 : "r"(a[0]), "r"(a[1]), "r"(a[2]), "r"(a[3]), "r"(b0), "r"(b1));
}
#define MBARRIER_INIT(mb, c) \
    asm volatile("mbarrier.init.shared.b64 [%0], %1;" :: "r"((uint32_t)(mb)), "r"((uint32_t)(c)) : "memory")
#define MBARRIER_EXPECT_TX(mb, b) \
    asm volatile("mbarrier.arrive.expect_tx.shared.b64 _, [%0], %1;" \
                 :: "r"((uint32_t)(mb)), "r"((uint32_t)(b)) : "memory")
#define MBARRIER_WAIT_PARITY(mb, par) do { \
    uint32_t _m = (uint32_t)(mb), _p = (uint32_t)(par), _d; \
    asm volatile("{\n\t.reg .pred p;\n\t" \
        "mbarrier.try_wait.parity.acquire.cta.shared::cta.b64 p, [%1], %2;\n\t" \
        "selp.b32 %0, 1, 0, p;\n\t}" : "=r"(_d) : "r"(_m), "r"(_p) : "memory"); \
    if (!_d) { \
        asm volatile("{\n\t.reg .pred P1;\n\tWL_%=:\n\t" \
            "mbarrier.try_wait.parity.acquire.cta.shared::cta.b64 P1, [%0], %1, 0x989680;\n\t" \
            "@P1 bra.uni WD_%=;\n\tbra.uni WL_%=;\n\tWD_%=:\n\t}" \
            :: "r"(_m), "r"(_p) : "memory"); \
    } } while (0)
__device__ __forceinline__ void tma2d(uint32_t dst, const void* map, int x, int y, uint32_t mb) {
    asm volatile(
        "cp.async.bulk.tensor.2d.shared::cta.global.tile.mbarrier::complete_tx::bytes "
        "[%0], [%1, {%2, %3}], [%4];"
        :: "r"(dst), "l"(map), "r"(x), "r"(y), "r"(mb) : "memory");
}
#define SW128(o) ((o) ^ (((o) >> 3) & 0x70u))

// ---------------- fp16 cast + zero kernels ----------------
__global__ void k_cast4(const float4* __restrict__ in, __half2* __restrict__ o, int total4) {
    int i = blockIdx.x * blockDim.x + threadIdx.x;
    if (i >= total4) return;
    float4 v = in[i];
    o[2 * i]     = __floats2half2_rn(v.x, v.y);
    o[2 * i + 1] = __floats2half2_rn(v.z, v.w);
}
__global__ void k_castT(const float* __restrict__ W, __half* __restrict__ o, int K, int N) {
    int i = blockIdx.x * blockDim.x + threadIdx.x;
    if (i >= K * N) return;
    int k = i / N, n = i % N;
    o[(size_t)n * K + k] = __float2half_rn(W[i]);
}
__global__ void k_zero5(float* a, float* b, float* c, float* d, float* e, int n1, int n2) {
    int i = blockIdx.x * blockDim.x + threadIdx.x;
    if (i < n1) { a[i] = 0.f; b[i] = 0.f; }
    if (i < n2) { c[i] = 0.f; d[i] = 0.f; e[i] = 0.f; }
}

// ============== TMA HMMA GEMM: C[M,N] = A[M,K] @ B[N,K]^T ====================
// fp16 in, fp32 accum. Outputs: fp32 C and/or fp16 Ch (non-null ones).
// Optional fused attention logits (ss/sd/av/bv) or fused influence partial
// (yp/bp1/wp2: p[m] += sum_c relu(C[m,c]+bp1[c])*wp2[c], valid when N==128).
#define TG_STAGE 32768
#define TG_SMEM (1024 + 3 * TG_STAGE)

__global__ void __launch_bounds__(256, 2)
hgemm_tma(const __grid_constant__ CUtensorMap mA,
          const __grid_constant__ CUtensorMap mB,
          float* __restrict__ C, __half* __restrict__ Ch, int M, int N, int K, int ytile0,
          float* __restrict__ ss, float* __restrict__ sd,
          const float* __restrict__ av, const float* __restrict__ bv,
          float* __restrict__ yp, const float* __restrict__ bp1,
          const float* __restrict__ wp2) {
    extern __shared__ unsigned char smraw[];
    const uint32_t base0 = (smem_u32(smraw) + 1023u) & ~1023u;
    const uint32_t mbb = base0;
    const uint32_t tile0 = base0 + 1024;
    const int tid = threadIdx.x, wid = tid >> 5, lane = tid & 31;
    const int bm = (blockIdx.y + ytile0) * 128, bn = blockIdx.x * 128;
    const int wr = (wid >> 1) * 32, wn = (wid & 1) * 64;
    const int nc = K >> 6;

    if (tid == 0) {
        MBARRIER_INIT(mbb + 0, 1);
        MBARRIER_INIT(mbb + 8, 1);
        MBARRIER_INIT(mbb + 16, 1);
    }
    __syncthreads();

    if (tid == 0) {
#pragma unroll
        for (int s = 0; s < 2; s++) {
            uint32_t mb = mbb + 8u * s;
            uint32_t t = tile0 + (uint32_t)s * TG_STAGE;
            MBARRIER_EXPECT_TX(mb, TG_STAGE);
            tma2d(t,          &mA, s * 64, bm, mb);
            tma2d(t + 16384u, &mB, s * 64, bn, mb);
        }
    }

    float acc[2][8][4];
#pragma unroll
    for (int a = 0; a < 2; a++)
#pragma unroll
        for (int b = 0; b < 8; b++)
#pragma unroll
            for (int c = 0; c < 4; c++) acc[a][b][c] = 0.f;

    for (int i = 0; i < nc; i++) {
        const int b = i % 3;
        MBARRIER_WAIT_PARITY(mbb + 8u * b, (i / 3) & 1);
        __syncthreads();
        if (tid == 0 && i + 2 < nc) {
            const int nb = (i + 2) % 3;
            uint32_t mb = mbb + 8u * nb;
            uint32_t t = tile0 + (uint32_t)nb * TG_STAGE;
            MBARRIER_EXPECT_TX(mb, TG_STAGE);
            tma2d(t,          &mA, (i + 2) * 64, bm, mb);
            tma2d(t + 16384u, &mB, (i + 2) * 64, bn, mb);
        }

        const uint32_t tA = tile0 + (uint32_t)b * TG_STAGE;
        const uint32_t tB = tA + 16384u;
        const int gq = lane >> 3;
#pragma unroll
        for (int ks = 0; ks < 4; ks++) {
            uint32_t ar[2][4], br[4][4];
#pragma unroll
            for (int mt = 0; mt < 2; mt++) {
                uint32_t lin = (uint32_t)(wr + mt * 16 + (lane & 15)) * 128u
                             + (uint32_t)(ks * 32 + (lane >> 4) * 16);
                ldm4(ar[mt], tA + SW128(lin));
            }
#pragma unroll
            for (int bt = 0; bt < 4; bt++) {
                uint32_t lin = (uint32_t)(wn + bt * 16 + ((gq >> 1) << 3) + (lane & 7)) * 128u
                             + (uint32_t)(ks * 32 + (gq & 1) * 16);
                ldm4(br[bt], tB + SW128(lin));
            }
#pragma unroll
            for (int mt = 0; mt < 2; mt++)
#pragma unroll
                for (int j = 0; j < 8; j++) {
                    const int bt = j >> 1, p0 = (j & 1) * 2;
                    mma16816(acc[mt][j], ar[mt], br[bt][p0], br[bt][p0 + 1]);
                }
        }
    }

    // epilogue: fp32 and/or fp16 stores
#pragma unroll
    for (int mt = 0; mt < 2; mt++) {
        int m0 = bm + wr + mt * 16 + (lane >> 2);
#pragma unroll
        for (int j = 0; j < 8; j++) {
            int n0 = bn + wn + j * 8 + (lane & 3) * 2;
            if (C) {
                if (m0 < M)
                    *(float2*)&C[(size_t)m0 * N + n0] = make_float2(acc[mt][j][0], acc[mt][j][1]);
                if (m0 + 8 < M)
                    *(float2*)&C[(size_t)(m0 + 8) * N + n0] = make_float2(acc[mt][j][2], acc[mt][j][3]);
            }
            if (Ch) {
                if (m0 < M)
                    *(__half2*)&Ch[(size_t)m0 * N + n0] =
                        __floats2half2_rn(acc[mt][j][0], acc[mt][j][1]);
                if (m0 + 8 < M)
                    *(__half2*)&Ch[(size_t)(m0 + 8) * N + n0] =
                        __floats2half2_rn(acc[mt][j][2], acc[mt][j][3]);
            }
        }
    }

    // fused attention-logit partials
    if (ss) {
        const int Hh = N >> 8;            // heads (head width 256)
        const int h = bn >> 8;
        const int cb0 = (bn & 255) + wn + (lane & 3) * 2;
#pragma unroll
        for (int mt = 0; mt < 2; mt++) {
            int m0 = bm + wr + mt * 16 + (lane >> 2);
            float ps0 = 0.f, pd0 = 0.f, ps1 = 0.f, pd1 = 0.f;
#pragma unroll
            for (int j = 0; j < 8; j++) {
                int cb = cb0 + j * 8;
                float a0 = av[h * 256 + cb], a1 = av[h * 256 + cb + 1];
                float d0 = bv[h * 256 + cb], d1 = bv[h * 256 + cb + 1];
                ps0 += acc[mt][j][0] * a0 + acc[mt][j][1] * a1;
                pd0 += acc[mt][j][0] * d0 + acc[mt][j][1] * d1;
                ps1 += acc[mt][j][2] * a0 + acc[mt][j][3] * a1;
                pd1 += acc[mt][j][2] * d0 + acc[mt][j][3] * d1;
            }
#pragma unroll
            for (int o = 1; o < 4; o <<= 1) {
                ps0 += __shfl_xor_sync(0xffffffffu, ps0, o);
                pd0 += __shfl_xor_sync(0xffffffffu, pd0, o);
                ps1 += __shfl_xor_sync(0xffffffffu, ps1, o);
                pd1 += __shfl_xor_sync(0xffffffffu, pd1, o);
            }
            if ((lane & 3) == 0) {
                if (m0 < M) {
                    atomicAdd(&ss[m0 * Hh + h], ps0);
                    atomicAdd(&sd[m0 * Hh + h], pd0);
                }
                if (m0 + 8 < M) {
                    atomicAdd(&ss[(m0 + 8) * Hh + h], ps1);
                    atomicAdd(&sd[(m0 + 8) * Hh + h], pd1);
                }
            }
        }
    }

    // fused influence partial (N == 128, bn == 0)
    if (yp) {
#pragma unroll
        for (int mt = 0; mt < 2; mt++) {
            int m0 = bm + wr + mt * 16 + (lane >> 2);
            float p0 = 0.f, p1 = 0.f;
#pragma unroll
            for (int j = 0; j < 8; j++) {
                int n0 = wn + j * 8 + (lane & 3) * 2;
                float w0 = wp2[n0], w1 = wp2[n0 + 1];
                float b0 = bp1[n0], b1e = bp1[n0 + 1];
                p0 += fmaxf(acc[mt][j][0] + b0, 0.f) * w0 + fmaxf(acc[mt][j][1] + b1e, 0.f) * w1;
                p1 += fmaxf(acc[mt][j][2] + b0, 0.f) * w0 + fmaxf(acc[mt][j][3] + b1e, 0.f) * w1;
            }
#pragma unroll
            for (int o = 1; o < 4; o <<= 1) {
                p0 += __shfl_xor_sync(0xffffffffu, p0, o);
                p1 += __shfl_xor_sync(0xffffffffu, p1, o);
            }
            if ((lane & 3) == 0) {
                if (m0 < M) atomicAdd(&yp[m0], p0);
                if (m0 + 8 < M) atomicAdd(&yp[m0 + 8], p1);
            }
        }
    }
}

// ---------------- CSR build ----------------
__global__ void k_deg_init(int n) {
    int i = blockIdx.x * blockDim.x + threadIdx.x;
    if (i < n) g_deg[i] = 1;
}
__global__ void k_deg_count(const int* __restrict__ dst, int e) {
    int i = blockIdx.x * blockDim.x + threadIdx.x;
    if (i < e) atomicAdd(&g_deg[dst[i]], 1);
}
__global__ void k_scan(int n) {
    __shared__ int sums[1024];
    int tid = threadIdx.x;
    int chunk = (n + 1023) / 1024;
    int lo = tid * chunk, hi = min(lo + chunk, n);
    int s = 0;
    for (int i = lo; i < hi; i++) s += g_deg[i];
    sums[tid] = s;
    __syncthreads();
    for (int d = 1; d < 1024; d <<= 1) {
        int v = (tid >= d) ? sums[tid - d] : 0;
        __syncthreads();
        sums[tid] += v;
        __syncthreads();
    }
    int base = (tid == 0) ? 0 : sums[tid - 1];
    for (int i = lo; i < hi; i++) {
        g_off[i] = base;
        g_cur[i] = base;
        base += g_deg[i];
    }
    if (tid == 1023) g_off[n] = sums[1023];
}
__global__ void k_fill(const int* __restrict__ src, const int* __restrict__ dst, int e, int n) {
    int i = blockIdx.x * blockDim.x + threadIdx.x;
    if (i >= e + n) return;
    int s, d;
    if (i < e) { s = src[i]; d = dst[i]; }
    else       { s = i - e;  d = i - e; }
    int pos = atomicAdd(&g_cur[d], 1);
    g_csrc[pos] = s;
}

// ---------------- grouped per-dst softmax + aggregation ----------------
__device__ __forceinline__ float lrelu(float x) { return x > 0.f ? x : 0.2f * x; }
__device__ __forceinline__ void acc8(float* a, uint4 v, float w) {
    float2 f;
    f = __half22float2(*(__half2*)&v.x); a[0] += f.x * w; a[1] += f.y * w;
    f = __half22float2(*(__half2*)&v.y); a[2] += f.x * w; a[3] += f.y * w;
    f = __half22float2(*(__half2*)&v.z); a[4] += f.x * w; a[5] += f.y * w;
    f = __half22float2(*(__half2*)&v.w); a[6] += f.x * w; a[7] += f.y * w;
}
__device__ __forceinline__ void acc4(float* a, uint2 v, float w) {
    float2 f;
    f = __half22float2(*(__half2*)&v.x); a[0] += f.x * w; a[1] += f.y * w;
    f = __half22float2(*(__half2*)&v.y); a[2] += f.x * w; a[3] += f.y * w;
}

template <int H, int C, int GSZ>
__global__ void __launch_bounds__(256)
k_agg(const __half* __restrict__ feat, const float* __restrict__ ss,
      const float* __restrict__ sd, const float* __restrict__ bias,
      float* __restrict__ out, __half* __restrict__ oh, int d0) {
    constexpr int NG  = 256 / GSZ;
    constexpr int CAP = 64;
    constexpr int HC  = H * C;
    constexpr int PH  = HC / GSZ;       // 8 (agg1) or 4 (agg2)
    const int t = threadIdx.x;
    const int g = t / GSZ, gt = t % GSZ;
    const int gw = gt >> 5, lane = gt & 31;
    const int d = d0 + blockIdx.x * NG + g;
    const int base = g_off[d], deg = g_off[d + 1] - base;
    const int capped = min(deg, CAP);
    const int barid = g + 1;

    __shared__ float s_e[NG][CAP * H];
    __shared__ int   s_idx[NG][CAP];
    __shared__ float s_m[NG][H], s_inv[NG][H];

#define GBAR() asm volatile("bar.sync %0, %1;" :: "r"(barid), "r"((int)GSZ) : "memory")

    {
        const int jj = (H == 1) ? gt : (gt >> 2);
        const int h  = (H == 1) ? 0 : (gt & 3);
        const float sdv = sd[d * H + h];
        for (int j0 = 0; j0 < capped; j0 += GSZ / H) {
            int j = j0 + jj;
            if (j < capped) {
                int s = g_csrc[base + j];
                if (h == 0) s_idx[g][j] = s;
                s_e[g][j * H + h] = lrelu(ss[s * H + h] + sdv);
            }
        }
    }
    GBAR();

    if (gw < H) {
        const int h = gw;
        const float sdv = sd[d * H + h];
        float mx = -1e30f;
        for (int j = lane; j < capped; j += 32) mx = fmaxf(mx, s_e[g][j * H + h]);
        for (int j = CAP + lane; j < deg; j += 32) {
            int s = g_csrc[base + j];
            mx = fmaxf(mx, lrelu(ss[s * H + h] + sdv));
        }
#pragma unroll
        for (int o = 16; o; o >>= 1) mx = fmaxf(mx, __shfl_xor_sync(0xffffffffu, mx, o));
        float sm = 0.f;
        for (int j = lane; j < capped; j += 32) sm += expf(s_e[g][j * H + h] - mx);
        for (int j = CAP + lane; j < deg; j += 32) {
            int s = g_csrc[base + j];
            sm += expf(lrelu(ss[s * H + h] + sdv) - mx);
        }
#pragma unroll
        for (int o = 16; o; o >>= 1) sm += __shfl_xor_sync(0xffffffffu, sm, o);
        if (lane == 0) { s_m[g][h] = mx; s_inv[g][h] = 1.f / (sm + 1e-16f); }
    }
    GBAR();

    {
        const int jj = (H == 1) ? gt : (gt >> 2);
        const int h  = (H == 1) ? 0 : (gt & 3);
        const float mh = s_m[g][h], iv = s_inv[g][h];
        for (int j0 = 0; j0 < capped; j0 += GSZ / H) {
            int j = j0 + jj;
            if (j < capped) s_e[g][j * H + h] = expf(s_e[g][j * H + h] - mh) * iv;
        }
    }
    GBAR();

    const int hh = (gt * PH) / C;   // warp-uniform
    float acc[PH];
#pragma unroll
    for (int k = 0; k < PH; k++) acc[k] = 0.f;
    const float* we = &s_e[g][0];
    const int* sidx = &s_idx[g][0];

    if (PH == 8) {
        const __half* fb = feat + gt * 8;
        uint4 b0 = make_uint4(0, 0, 0, 0), b1 = b0, b2 = b0, b3 = b0;
        if (capped > 0) b0 = *(const uint4*)(fb + (size_t)sidx[0] * HC);
        if (capped > 1) b1 = *(const uint4*)(fb + (size_t)sidx[1] * HC);
        if (capped > 2) b2 = *(const uint4*)(fb + (size_t)sidx[2] * HC);
        if (capped > 3) b3 = *(const uint4*)(fb + (size_t)sidx[3] * HC);
        int j = 0;
        for (; j + 4 <= capped; j += 4) {
            float w0 = we[(j + 0) * H + hh], w1 = we[(j + 1) * H + hh];
            float w2 = we[(j + 2) * H + hh], w3 = we[(j + 3) * H + hh];
            uint4 v0 = b0, v1 = b1, v2 = b2, v3 = b3;
            if (j + 4 < capped) b0 = *(const uint4*)(fb + (size_t)sidx[j + 4] * HC);
            if (j + 5 < capped) b1 = *(const uint4*)(fb + (size_t)sidx[j + 5] * HC);
            if (j + 6 < capped) b2 = *(const uint4*)(fb + (size_t)sidx[j + 6] * HC);
            if (j + 7 < capped) b3 = *(const uint4*)(fb + (size_t)sidx[j + 7] * HC);
            acc8(acc, v0, w0); acc8(acc, v1, w1); acc8(acc, v2, w2); acc8(acc, v3, w3);
        }
        if (j     < capped) acc8(acc, b0, we[(j + 0) * H + hh]);
        if (j + 1 < capped) acc8(acc, b1, we[(j + 1) * H + hh]);
        if (j + 2 < capped) acc8(acc, b2, we[(j + 2) * H + hh]);
    } else {
        const __half* fb = feat + gt * 4;
        uint2 b0 = make_uint2(0, 0), b1 = b0, b2 = b0, b3 = b0;
        if (capped > 0) b0 = *(const uint2*)(fb + (size_t)sidx[0] * HC);
        if (capped > 1) b1 = *(const uint2*)(fb + (size_t)sidx[1] * HC);
        if (capped > 2) b2 = *(const uint2*)(fb + (size_t)sidx[2] * HC);
        if (capped > 3) b3 = *(const uint2*)(fb + (size_t)sidx[3] * HC);
        int j = 0;
        for (; j + 4 <= capped; j += 4) {
            float w0 = we[(j + 0) * H + hh], w1 = we[(j + 1) * H + hh];
            float w2 = we[(j + 2) * H + hh], w3 = we[(j + 3) * H + hh];
            uint2 v0 = b0, v1 = b1, v2 = b2, v3 = b3;
            if (j + 4 < capped) b0 = *(const uint2*)(fb + (size_t)sidx[j + 4] * HC);
            if (j + 5 < capped) b1 = *(const uint2*)(fb + (size_t)sidx[j + 5] * HC);
            if (j + 6 < capped) b2 = *(const uint2*)(fb + (size_t)sidx[j + 6] * HC);
            if (j + 7 < capped) b3 = *(const uint2*)(fb + (size_t)sidx[j + 7] * HC);
            acc4(acc, v0, w0); acc4(acc, v1, w1); acc4(acc, v2, w2); acc4(acc, v3, w3);
        }
        if (j     < capped) acc4(acc, b0, we[(j + 0) * H + hh]);
        if (j + 1 < capped) acc4(acc, b1, we[(j + 1) * H + hh]);
        if (j + 2 < capped) acc4(acc, b2, we[(j + 2) * H + hh]);
    }

    if (deg > CAP) {
        const float mh = s_m[g][hh], iv = s_inv[g][hh];
        const float sdv = sd[d * H + hh];
        for (int j = CAP; j < deg; j++) {
            int s = g_csrc[base + j];
            float w = expf(lrelu(ss[s * H + hh] + sdv) - mh) * iv;
            if (PH == 8) acc8(acc, *(const uint4*)(feat + (size_t)s * HC + gt * 8), w);
            else         acc4(acc, *(const uint2*)(feat + (size_t)s * HC + gt * 4), w);
        }
    }

    const int c0 = gt * PH;
    float vv[PH];
#pragma unroll
    for (int k = 0; k < PH; k++) {
        float v = acc[k] + bias[c0 + k];
        vv[k] = v > 0.f ? v : expm1f(v);
    }
    if (out) {
#pragma unroll
        for (int k = 0; k < PH; k += 2)
            *(float2*)&out[(size_t)d * HC + c0 + k] = make_float2(vv[k], vv[k + 1]);
    }
#pragma unroll
    for (int k = 0; k < PH; k += 2)
        *(__half2*)&oh[(size_t)d * HC + c0 + k] = __floats2half2_rn(vv[k], vv[k + 1]);
#undef GBAR
}

// ---------------- graph mean + sigmoid ----------------
__global__ void k_zero_gf(float* gf) { gf[threadIdx.x] = 0.f; }
__global__ void k_colsum(const float* __restrict__ h, float* __restrict__ gf) {
    float acc = 0.f;
    int t = threadIdx.x;
    for (int r = blockIdx.x; r < NN; r += gridDim.x) acc += h[(size_t)r * F2 + t];
    atomicAdd(&gf[t], acc);
}
__global__ void k_scale_gf(float* gf) { gf[threadIdx.x] *= (1.0f / (float)NN); }

__global__ void k_sigmoid(const float* __restrict__ yp, const float* __restrict__ bp2,
                          float* __restrict__ infl, int n, int i0) {
    int i = blockIdx.x * blockDim.x + threadIdx.x;
    if (i < n) infl[i0 + i] = 1.f / (1.f + expf(-(yp[i0 + i] + bp2[0])));
}

// ---------------- host: tensor-map builder ----------------
typedef CUresult (*PFN_encodeTiled)(
    CUtensorMap*, CUtensorMapDataType, cuuint32_t, void*,
    const cuuint64_t*, const cuuint64_t*, const cuuint32_t*, const cuuint32_t*,
    CUtensorMapInterleave, CUtensorMapSwizzle, CUtensorMapL2promotion,
    CUtensorMapFloatOOBfill);

static CUtensorMap make_map(PFN_encodeTiled enc, void* base, int K, int rows) {
    CUtensorMap m;
    cuuint64_t dims[2]    = {(cuuint64_t)K, (cuuint64_t)rows};
    cuuint64_t strides[1] = {(cuuint64_t)K * 2};
    cuuint32_t box[2]     = {64, 128};
    cuuint32_t es[2]      = {1, 1};
    enc(&m, CU_TENSOR_MAP_DATA_TYPE_FLOAT16, 2, base, dims, strides, box, es,
        CU_TENSOR_MAP_INTERLEAVE_NONE, CU_TENSOR_MAP_SWIZZLE_128B,
        CU_TENSOR_MAP_L2_PROMOTION_L2_128B, CU_TENSOR_MAP_FLOAT_OOB_FILL_NONE);
    return m;
}

// ---------------- launch ----------------
extern "C" void kernel_launch(void* const* d_in, const int* in_sizes, int n_in,
                              void* d_out, int out_size) {
    const float* x   = (const float*)d_in[0];
    const int*   eidx = (const int*)d_in[1];
    const float* W1  = (const float*)d_in[2];
    const float* as1 = (const float*)d_in[3];
    const float* ad1 = (const float*)d_in[4];
    const float* b1  = (const float*)d_in[5];
    const float* W2  = (const float*)d_in[6];
    const float* as2 = (const float*)d_in[7];
    const float* ad2 = (const float*)d_in[8];
    const float* b2  = (const float*)d_in[9];
    const float* Wp1 = (const float*)d_in[10];
    const float* bp1 = (const float*)d_in[11];
    const float* Wp2 = (const float*)d_in[12];
    const float* bp2 = (const float*)d_in[13];

    const int* src = eidx;
    const int* dst = eidx + EE;

    float* out   = (float*)d_out;
    float* out_h = out;
    float* out_g = out + (size_t)NN * F2;
    float* out_i = out_g + F2;

    float *p_yp, *p_ss1, *p_sd1, *p_ss2, *p_sd2;
    __half *p_xh, *p_w1h, *p_h1h, *p_o1h, *p_w2h, *p_h2h, *p_hh, *p_wph;
    cudaGetSymbolAddress((void**)&p_yp, g_yp);
    cudaGetSymbolAddress((void**)&p_ss1, g_ss1);
    cudaGetSymbolAddress((void**)&p_sd1, g_sd1);
    cudaGetSymbolAddress((void**)&p_ss2, g_ss2);
    cudaGetSymbolAddress((void**)&p_sd2, g_sd2);
    cudaGetSymbolAddress((void**)&p_xh,  g_xh);
    cudaGetSymbolAddress((void**)&p_w1h, g_w1h);
    cudaGetSymbolAddress((void**)&p_h1h, g_h1h);
    cudaGetSymbolAddress((void**)&p_o1h, g_o1h);
    cudaGetSymbolAddress((void**)&p_w2h, g_w2h);
    cudaGetSymbolAddress((void**)&p_h2h, g_h2h);
    cudaGetSymbolAddress((void**)&p_hh,  g_hh);
    cudaGetSymbolAddress((void**)&p_wph, g_wph);

    PFN_encodeTiled enc = nullptr;
    cudaGetDriverEntryPoint("cuTensorMapEncodeTiled", (void**)&enc, cudaEnableDefault);

    CUtensorMap mA1 = make_map(enc, p_xh,  FIN, NN);
    CUtensorMap mB1 = make_map(enc, p_w1h, FIN, F1);
    CUtensorMap mA2 = make_map(enc, p_o1h, F1,  NN);
    CUtensorMap mB2 = make_map(enc, p_w2h, F1,  F2);
    CUtensorMap mA3 = make_map(enc, p_hh,  F2,  NN);
    CUtensorMap mB3 = make_map(enc, p_wph, F2, PHID);

    cudaFuncSetAttribute(hgemm_tma, cudaFuncAttributeMaxDynamicSharedMemorySize, TG_SMEM);

    static cudaStream_t s1 = nullptr;
    static cudaEvent_t evF1 = nullptr, evW1 = nullptr, evJ1 = nullptr, evA1lo = nullptr,
                       evS1a = nullptr, evA2lo = nullptr, evA2hi = nullptr, evJ2 = nullptr;
    if (!s1) {
        cudaStreamCreateWithFlags(&s1, cudaStreamNonBlocking);
        cudaEventCreateWithFlags(&evF1,  cudaEventDisableTiming);
        cudaEventCreateWithFlags(&evW1,  cudaEventDisableTiming);
        cudaEventCreateWithFlags(&evJ1,  cudaEventDisableTiming);
        cudaEventCreateWithFlags(&evA1lo, cudaEventDisableTiming);
        cudaEventCreateWithFlags(&evS1a, cudaEventDisableTiming);
        cudaEventCreateWithFlags(&evA2lo, cudaEventDisableTiming);
        cudaEventCreateWithFlags(&evA2hi, cudaEventDisableTiming);
        cudaEventCreateWithFlags(&evJ2,  cudaEventDisableTiming);
    }

    // ---- fork 1: W1 cast first (GEMM1 dep), then W2/Wp1 casts + CSR ----
    cudaEventRecord(evF1, 0);
    cudaStreamWaitEvent(s1, evF1, 0);
    k_castT<<<(FIN * F1 + 255) / 256, 256, 0, s1>>>(W1, p_w1h, FIN, F1);
    cudaEventRecord(evW1, s1);
    k_castT<<<(F1 * F2 + 255) / 256, 256, 0, s1>>>(W2, p_w2h, F1, F2);
    k_castT<<<(F2 * PHID + 255) / 256, 256, 0, s1>>>(Wp1, p_wph, F2, PHID);
    k_deg_init <<<(NN + 255) / 256, 256, 0, s1>>>(NN);
    k_deg_count<<<(EE + 255) / 256, 256, 0, s1>>>(dst, EE);
    k_scan<<<1, 1024, 0, s1>>>(NN);
    k_fill<<<(ETOT + 255) / 256, 256, 0, s1>>>(src, dst, EE, NN);
    cudaEventRecord(evJ1, s1);

    // ---- main: zero logits+partial, cast x (vectorized) -> GEMM1 ----
    k_zero5<<<(NN * HH1 + 255) / 256, 256>>>(p_ss1, p_sd1, p_ss2, p_sd2, p_yp, NN * HH1, NN);
    k_cast4<<<(NN * FIN / 4 + 255) / 256, 256>>>((const float4*)x, (__half2*)p_xh, NN * FIN / 4);
    cudaStreamWaitEvent(0, evW1, 0);
    hgemm_tma<<<dim3(F1 / 128, TLO + THI), 256, TG_SMEM>>>(mA1, mB1, nullptr, p_h1h,
                                                           NN, F1, FIN, 0,
                                                           p_ss1, p_sd1, as1, ad1,
                                                           nullptr, nullptr, nullptr);
    cudaStreamWaitEvent(0, evJ1, 0);

    // ---- agg1 split-pipeline with GEMM2 (fp16 out + fused ss2/sd2) ----
    k_agg<HH1, HD, 128><<<NSPLIT / 2, 256>>>(p_h1h, p_ss1, p_sd1, b1, nullptr, p_o1h, 0);
    cudaEventRecord(evA1lo, 0);
    cudaStreamWaitEvent(s1, evA1lo, 0);
    hgemm_tma<<<dim3(F2 / 128, TLO), 256, TG_SMEM, s1>>>(mA2, mB2, nullptr, p_h2h,
                                                         NN, F2, F1, 0,
                                                         p_ss2, p_sd2, as2, ad2,
                                                         nullptr, nullptr, nullptr);
    cudaEventRecord(evS1a, s1);

    k_agg<HH1, HD, 128><<<(NN - NSPLIT) / 2, 256>>>(p_h1h, p_ss1, p_sd1, b1, nullptr, p_o1h, NSPLIT);
    hgemm_tma<<<dim3(F2 / 128, THI), 256, TG_SMEM>>>(mA2, mB2, nullptr, p_h2h,
                                                     NN, F2, F1, TLO,
                                                     p_ss2, p_sd2, as2, ad2,
                                                     nullptr, nullptr, nullptr);
    cudaStreamWaitEvent(0, evS1a, 0);

    // ---- agg2 split-pipeline with GEMM3 (fused influence partial) ----
    k_agg<1, F2, 64><<<NSPLIT / 4, 256>>>(p_h2h, p_ss2, p_sd2, b2, out_h, p_hh, 0);
    cudaEventRecord(evA2lo, 0);
    cudaStreamWaitEvent(s1, evA2lo, 0);
    hgemm_tma<<<dim3(1, TLO), 256, TG_SMEM, s1>>>(mA3, mB3, nullptr, nullptr,
                                                  NN, PHID, F2, 0,
                                                  nullptr, nullptr, nullptr, nullptr,
                                                  p_yp, bp1, Wp2);
    k_sigmoid<<<(NSPLIT + 255) / 256, 256, 0, s1>>>(p_yp, bp2, out_i, NSPLIT, 0);

    k_agg<1, F2, 64><<<(NN - NSPLIT) / 4, 256>>>(p_h2h, p_ss2, p_sd2, b2, out_h, p_hh, NSPLIT);
    cudaEventRecord(evA2hi, 0);

    // side: graph mean (needs full out_h)
    cudaStreamWaitEvent(s1, evA2hi, 0);
    k_zero_gf<<<1, F2, 0, s1>>>(out_g);
    k_colsum<<<160, F2, 0, s1>>>(out_h, out_g);
    k_scale_gf<<<1, F2, 0, s1>>>(out_g);
    cudaEventRecord(evJ2, s1);

    // main: GEMM3_hi (fused influence) + sigmoid_hi
    hgemm_tma<<<dim3(1, THI), 256, TG_SMEM>>>(mA3, mB3, nullptr, nullptr,
                                              NN, PHID, F2, TLO,
                                              nullptr, nullptr, nullptr, nullptr,
                                              p_yp, bp1, Wp2);
    k_sigmoid<<<(NN - NSPLIT + 255) / 256, 256>>>(p_yp, bp2, out_i, NN - NSPLIT, NSPLIT);
    cudaStreamWaitEvent(0, evJ2, 0);
}

// round 16
// speedup vs baseline: 1.1534x; 1.0015x over previous
#include <cuda_runtime.h>
#include <cuda.h>
#include <cuda_fp16.h>
#include <math.h>
#include <cstdint>

#define NN   20000
#define EE   320000
#define ETOT 340000
#define FIN  384
#define F1   1024
#define HH1  4
#define HD   256
#define F2   256
#define PHID 128
#define NSPLIT 10112          // 79 row tiles of 128; divisible by 4
#define TLO 79
#define THI 78

// ---------------- scratch (static device globals; no runtime alloc) ----------
__device__ float g_yp[NN];            // influence partial (atomic accum)
__device__ float g_ss1[NN * HH1];
__device__ float g_sd1[NN * HH1];
__device__ float g_ss2[NN];
__device__ float g_sd2[NN];
__device__ int   g_deg[NN];
__device__ int   g_off[NN + 1];
__device__ int   g_cur[NN];
__device__ int   g_csrc[ETOT];
// fp16 planes (A row-major [M,K]; B transposed [N,K])
__device__ __align__(128) __half g_xh [(size_t)NN * FIN];
__device__ __align__(128) __half g_w1h[(size_t)F1 * FIN];
__device__ __align__(128) __half g_h1h[(size_t)NN * F1];
__device__ __align__(128) __half g_o1h[(size_t)NN * F1];
__device__ __align__(128) __half g_w2h[(size_t)F2 * F1];
__device__ __align__(128) __half g_h2h[(size_t)NN * F2];
__device__ __align__(128) __half g_hh [(size_t)NN * F2];
__device__ __align__(128) __half g_wph[(size_t)PHID * F2];

// ---------------- helpers ----------------
__device__ __forceinline__ uint32_t smem_u32(const void* p) {
    uint32_t a;
    asm("{ .reg .u64 t; cvta.to.shared.u64 t, %1; cvt.u32.u64 %0, t; }" : "=r"(a) : "l"(p));
    return a;
}
__device__ __forceinline__ void ldm4(uint32_t* r, uint32_t a) {
    asm volatile("ldmatrix.sync.aligned.m8n8.x4.shared.b16 {%0,%1,%2,%3}, [%4];"
                 : "=r"(r[0]), "=r"(r[1]), "=r"(r[2]), "=r"(r[3]) : "r"(a));
}
__device__ __forceinline__ void mma16816(float* c, const uint32_t* a, uint32_t b0, uint32_t b1) {
    asm volatile("mma.sync.aligned.m16n8k16.row.col.f32.f16.f16.f32 "
                 "{%0,%1,%2,%3}, {%4,%5,%6,%7}, {%8,%9}, {%0,%1,%2,%3};"
                 : "+f"(c[0]), "+f"(c[1]), "+f"(c[2]), "+f"(c[3])
                 : "r"(a[0]), "r"(a[1]), "r"(a[2]), "r"(a[3]), "r"(b0), "r"(b1));
}
#define MBARRIER_INIT(mb, c) \
    asm volatile("mbarrier.init.shared.b64 [%0], %1;" :: "r"((uint32_t)(mb)), "r"((uint32_t)(c)) : "memory")
#define MBARRIER_EXPECT_TX(mb, b) \
    asm volatile("mbarrier.arrive.expect_tx.shared.b64 _, [%0], %1;" \
                 :: "r"((uint32_t)(mb)), "r"((uint32_t)(b)) : "memory")
#define MBARRIER_WAIT_PARITY(mb, par) do { \
    uint32_t _m = (uint32_t)(mb), _p = (uint32_t)(par), _d; \
    asm volatile("{\n\t.reg .pred p;\n\t" \
        "mbarrier.try_wait.parity.acquire.cta.shared::cta.b64 p, [%1], %2;\n\t" \
        "selp.b32 %0, 1, 0, p;\n\t}" : "=r"(_d) : "r"(_m), "r"(_p) : "memory"); \
    if (!_d) { \
        asm volatile("{\n\t.reg .pred P1;\n\tWL_%=:\n\t" \
            "mbarrier.try_wait.parity.acquire.cta.shared::cta.b64 P1, [%0], %1, 0x989680;\n\t" \
            "@P1 bra.uni WD_%=;\n\tbra.uni WL_%=;\n\tWD_%=:\n\t}" \
            :: "r"(_m), "r"(_p) : "memory"); \
    } } while (0)
__device__ __forceinline__ void tma2d(uint32_t dst, const void* map, int x, int y, uint32_t mb) {
    asm volatile(
        "cp.async.bulk.tensor.2d.shared::cta.global.tile.mbarrier::complete_tx::bytes "
        "[%0], [%1, {%2, %3}], [%4];"
        :: "r"(dst), "l"(map), "r"(x), "r"(y), "r"(mb) : "memory");
}
#define SW128(o) ((o) ^ (((o) >> 3) & 0x70u))

// ---------------- fp16 cast + zero kernels ----------------
__global__ void k_cast4(const float4* __restrict__ in, __half2* __restrict__ o, int total4) {
    int i = blockIdx.x * blockDim.x + threadIdx.x;
    if (i >= total4) return;
    float4 v = in[i];
    o[2 * i]     = __floats2half2_rn(v.x, v.y);
    o[2 * i + 1] = __floats2half2_rn(v.z, v.w);
}
// W [K,N] fp32 -> [N,K] fp16 (transposed); 2 k's per thread
__global__ void k_castT2(const float* __restrict__ W, __half* __restrict__ o, int K, int N) {
    int i = blockIdx.x * blockDim.x + threadIdx.x;
    int half_total = (K / 2) * N;
    if (i >= half_total) return;
    int k2 = i / N, n = i % N;
    int k = k2 * 2;
    __half2 v = __floats2half2_rn(W[(size_t)k * N + n], W[(size_t)(k + 1) * N + n]);
    *(__half2*)&o[(size_t)n * K + k] = v;
}
__global__ void k_zeroinit(float* a, float* b, float* c, float* d, float* e,
                           int* deg, int n1, int n2) {
    int i = blockIdx.x * blockDim.x + threadIdx.x;
    if (i < n1) { a[i] = 0.f; b[i] = 0.f; }
    if (i < n2) { c[i] = 0.f; d[i] = 0.f; e[i] = 0.f; deg[i] = 1; }
}

// ============== TMA HMMA GEMM: C[M,N] = A[M,K] @ B[N,K]^T ====================
// fp16 in, fp32 accum. Outputs: fp32 C and/or fp16 Ch (non-null ones).
// Optional fused attention logits (ss/sd/av/bv) or fused influence partial
// (yp/bp1/wp2: p[m] += sum_c relu(C[m,c]+bp1[c])*wp2[c], valid when N==128).
#define TG_STAGE 32768
#define TG_SMEM (1024 + 3 * TG_STAGE)

__global__ void __launch_bounds__(256, 2)
hgemm_tma(const __grid_constant__ CUtensorMap mA,
          const __grid_constant__ CUtensorMap mB,
          float* __restrict__ C, __half* __restrict__ Ch, int M, int N, int K, int ytile0,
          float* __restrict__ ss, float* __restrict__ sd,
          const float* __restrict__ av, const float* __restrict__ bv,
          float* __restrict__ yp, const float* __restrict__ bp1,
          const float* __restrict__ wp2) {
    extern __shared__ unsigned char smraw[];
    const uint32_t base0 = (smem_u32(smraw) + 1023u) & ~1023u;
    const uint32_t mbb = base0;
    const uint32_t tile0 = base0 + 1024;
    const int tid = threadIdx.x, wid = tid >> 5, lane = tid & 31;
    const int bm = (blockIdx.y + ytile0) * 128, bn = blockIdx.x * 128;
    const int wr = (wid >> 1) * 32, wn = (wid & 1) * 64;
    const int nc = K >> 6;

    if (tid == 0) {
        MBARRIER_INIT(mbb + 0, 1);
        MBARRIER_INIT(mbb + 8, 1);
        MBARRIER_INIT(mbb + 16, 1);
    }
    __syncthreads();

    if (tid == 0) {
#pragma unroll
        for (int s = 0; s < 2; s++) {
            uint32_t mb = mbb + 8u * s;
            uint32_t t = tile0 + (uint32_t)s * TG_STAGE;
            MBARRIER_EXPECT_TX(mb, TG_STAGE);
            tma2d(t,          &mA, s * 64, bm, mb);
            tma2d(t + 16384u, &mB, s * 64, bn, mb);
        }
    }

    float acc[2][8][4];
#pragma unroll
    for (int a = 0; a < 2; a++)
#pragma unroll
        for (int b = 0; b < 8; b++)
#pragma unroll
            for (int c = 0; c < 4; c++) acc[a][b][c] = 0.f;

    for (int i = 0; i < nc; i++) {
        const int b = i % 3;
        MBARRIER_WAIT_PARITY(mbb + 8u * b, (i / 3) & 1);
        __syncthreads();
        if (tid == 0 && i + 2 < nc) {
            const int nb = (i + 2) % 3;
            uint32_t mb = mbb + 8u * nb;
            uint32_t t = tile0 + (uint32_t)nb * TG_STAGE;
            MBARRIER_EXPECT_TX(mb, TG_STAGE);
            tma2d(t,          &mA, (i + 2) * 64, bm, mb);
            tma2d(t + 16384u, &mB, (i + 2) * 64, bn, mb);
        }

        const uint32_t tA = tile0 + (uint32_t)b * TG_STAGE;
        const uint32_t tB = tA + 16384u;
        const int gq = lane >> 3;
#pragma unroll
        for (int ks = 0; ks < 4; ks++) {
            uint32_t ar[2][4], br[4][4];
#pragma unroll
            for (int mt = 0; mt < 2; mt++) {
                uint32_t lin = (uint32_t)(wr + mt * 16 + (lane & 15)) * 128u
                             + (uint32_t)(ks * 32 + (lane >> 4) * 16);
                ldm4(ar[mt], tA + SW128(lin));
            }
#pragma unroll
            for (int bt = 0; bt < 4; bt++) {
                uint32_t lin = (uint32_t)(wn + bt * 16 + ((gq >> 1) << 3) + (lane & 7)) * 128u
                             + (uint32_t)(ks * 32 + (gq & 1) * 16);
                ldm4(br[bt], tB + SW128(lin));
            }
#pragma unroll
            for (int mt = 0; mt < 2; mt++)
#pragma unroll
                for (int j = 0; j < 8; j++) {
                    const int bt = j >> 1, p0 = (j & 1) * 2;
                    mma16816(acc[mt][j], ar[mt], br[bt][p0], br[bt][p0 + 1]);
                }
        }
    }

    // epilogue: fp32 and/or fp16 stores
#pragma unroll
    for (int mt = 0; mt < 2; mt++) {
        int m0 = bm + wr + mt * 16 + (lane >> 2);
#pragma unroll
        for (int j = 0; j < 8; j++) {
            int n0 = bn + wn + j * 8 + (lane & 3) * 2;
            if (C) {
                if (m0 < M)
                    *(float2*)&C[(size_t)m0 * N + n0] = make_float2(acc[mt][j][0], acc[mt][j][1]);
                if (m0 + 8 < M)
                    *(float2*)&C[(size_t)(m0 + 8) * N + n0] = make_float2(acc[mt][j][2], acc[mt][j][3]);
            }
            if (Ch) {
                if (m0 < M)
                    *(__half2*)&Ch[(size_t)m0 * N + n0] =
                        __floats2half2_rn(acc[mt][j][0], acc[mt][j][1]);
                if (m0 + 8 < M)
                    *(__half2*)&Ch[(size_t)(m0 + 8) * N + n0] =
                        __floats2half2_rn(acc[mt][j][2], acc[mt][j][3]);
            }
        }
    }

    // fused attention-logit partials
    if (ss) {
        const int Hh = N >> 8;            // heads (head width 256)
        const int h = bn >> 8;
        const int cb0 = (bn & 255) + wn + (lane & 3) * 2;
#pragma unroll
        for (int mt = 0; mt < 2; mt++) {
            int m0 = bm + wr + mt * 16 + (lane >> 2);
            float ps0 = 0.f, pd0 = 0.f, ps1 = 0.f, pd1 = 0.f;
#pragma unroll
            for (int j = 0; j < 8; j++) {
                int cb = cb0 + j * 8;
                float a0 = av[h * 256 + cb], a1 = av[h * 256 + cb + 1];
                float d0 = bv[h * 256 + cb], d1 = bv[h * 256 + cb + 1];
                ps0 += acc[mt][j][0] * a0 + acc[mt][j][1] * a1;
                pd0 += acc[mt][j][0] * d0 + acc[mt][j][1] * d1;
                ps1 += acc[mt][j][2] * a0 + acc[mt][j][3] * a1;
                pd1 += acc[mt][j][2] * d0 + acc[mt][j][3] * d1;
            }
#pragma unroll
            for (int o = 1; o < 4; o <<= 1) {
                ps0 += __shfl_xor_sync(0xffffffffu, ps0, o);
                pd0 += __shfl_xor_sync(0xffffffffu, pd0, o);
                ps1 += __shfl_xor_sync(0xffffffffu, ps1, o);
                pd1 += __shfl_xor_sync(0xffffffffu, pd1, o);
            }
            if ((lane & 3) == 0) {
                if (m0 < M) {
                    atomicAdd(&ss[m0 * Hh + h], ps0);
                    atomicAdd(&sd[m0 * Hh + h], pd0);
                }
                if (m0 + 8 < M) {
                    atomicAdd(&ss[(m0 + 8) * Hh + h], ps1);
                    atomicAdd(&sd[(m0 + 8) * Hh + h], pd1);
                }
            }
        }
    }

    // fused influence partial (N == 128, bn == 0)
    if (yp) {
#pragma unroll
        for (int mt = 0; mt < 2; mt++) {
            int m0 = bm + wr + mt * 16 + (lane >> 2);
            float p0 = 0.f, p1 = 0.f;
#pragma unroll
            for (int j = 0; j < 8; j++) {
                int n0 = wn + j * 8 + (lane & 3) * 2;
                float w0 = wp2[n0], w1 = wp2[n0 + 1];
                float b0 = bp1[n0], b1e = bp1[n0 + 1];
                p0 += fmaxf(acc[mt][j][0] + b0, 0.f) * w0 + fmaxf(acc[mt][j][1] + b1e, 0.f) * w1;
                p1 += fmaxf(acc[mt][j][2] + b0, 0.f) * w0 + fmaxf(acc[mt][j][3] + b1e, 0.f) * w1;
            }
#pragma unroll
            for (int o = 1; o < 4; o <<= 1) {
                p0 += __shfl_xor_sync(0xffffffffu, p0, o);
                p1 += __shfl_xor_sync(0xffffffffu, p1, o);
            }
            if ((lane & 3) == 0) {
                if (m0 < M) atomicAdd(&yp[m0], p0);
                if (m0 + 8 < M) atomicAdd(&yp[m0 + 8], p1);
            }
        }
    }
}

// ---------------- CSR build ----------------
__global__ void k_deg_count(const int* __restrict__ dst, int e) {
    int i = blockIdx.x * blockDim.x + threadIdx.x;
    if (i < e) atomicAdd(&g_deg[dst[i]], 1);
}
__global__ void k_scan(int n) {
    __shared__ int sums[1024];
    int tid = threadIdx.x;
    int chunk = (n + 1023) / 1024;
    int lo = tid * chunk, hi = min(lo + chunk, n);
    int s = 0;
    for (int i = lo; i < hi; i++) s += g_deg[i];
    sums[tid] = s;
    __syncthreads();
    for (int d = 1; d < 1024; d <<= 1) {
        int v = (tid >= d) ? sums[tid - d] : 0;
        __syncthreads();
        sums[tid] += v;
        __syncthreads();
    }
    int base = (tid == 0) ? 0 : sums[tid - 1];
    for (int i = lo; i < hi; i++) {
        g_off[i] = base;
        g_cur[i] = base;
        base += g_deg[i];
    }
    if (tid == 1023) g_off[n] = sums[1023];
}
__global__ void k_fill(const int* __restrict__ src, const int* __restrict__ dst, int e, int n) {
    int i = blockIdx.x * blockDim.x + threadIdx.x;
    if (i >= e + n) return;
    int s, d;
    if (i < e) { s = src[i]; d = dst[i]; }
    else       { s = i - e;  d = i - e; }
    int pos = atomicAdd(&g_cur[d], 1);
    g_csrc[pos] = s;
}

// ---------------- grouped per-dst softmax + aggregation ----------------
__device__ __forceinline__ float lrelu(float x) { return x > 0.f ? x : 0.2f * x; }
__device__ __forceinline__ void acc8(float* a, uint4 v, float w) {
    float2 f;
    f = __half22float2(*(__half2*)&v.x); a[0] += f.x * w; a[1] += f.y * w;
    f = __half22float2(*(__half2*)&v.y); a[2] += f.x * w; a[3] += f.y * w;
    f = __half22float2(*(__half2*)&v.z); a[4] += f.x * w; a[5] += f.y * w;
    f = __half22float2(*(__half2*)&v.w); a[6] += f.x * w; a[7] += f.y * w;
}
__device__ __forceinline__ void acc4(float* a, uint2 v, float w) {
    float2 f;
    f = __half22float2(*(__half2*)&v.x); a[0] += f.x * w; a[1] += f.y * w;
    f = __half22float2(*(__half2*)&v.y); a[2] += f.x * w; a[3] += f.y * w;
}

template <int H, int C, int GSZ>
__global__ void __launch_bounds__(256)
k_agg(const __half* __restrict__ feat, const float* __restrict__ ss,
      const float* __restrict__ sd, const float* __restrict__ bias,
      float* __restrict__ out, __half* __restrict__ oh, int d0) {
    constexpr int NG  = 256 / GSZ;
    constexpr int CAP = 64;
    constexpr int HC  = H * C;
    constexpr int PH  = HC / GSZ;       // 8 (agg1) or 4 (agg2)
    const int t = threadIdx.x;
    const int g = t / GSZ, gt = t % GSZ;
    const int gw = gt >> 5, lane = gt & 31;
    const int d = d0 + blockIdx.x * NG + g;
    const int base = g_off[d], deg = g_off[d + 1] - base;
    const int capped = min(deg, CAP);
    const int barid = g + 1;

    __shared__ float s_e[NG][CAP * H];
    __shared__ int   s_idx[NG][CAP];
    __shared__ float s_m[NG][H], s_inv[NG][H];

#define GBAR() asm volatile("bar.sync %0, %1;" :: "r"(barid), "r"((int)GSZ) : "memory")

    {
        const int jj = (H == 1) ? gt : (gt >> 2);
        const int h  = (H == 1) ? 0 : (gt & 3);
        const float sdv = sd[d * H + h];
        for (int j0 = 0; j0 < capped; j0 += GSZ / H) {
            int j = j0 + jj;
            if (j < capped) {
                int s = g_csrc[base + j];
                if (h == 0) s_idx[g][j] = s;
                s_e[g][j * H + h] = lrelu(ss[s * H + h] + sdv);
            }
        }
    }
    GBAR();

    if (gw < H) {
        const int h = gw;
        const float sdv = sd[d * H + h];
        float mx = -1e30f;
        for (int j = lane; j < capped; j += 32) mx = fmaxf(mx, s_e[g][j * H + h]);
        for (int j = CAP + lane; j < deg; j += 32) {
            int s = g_csrc[base + j];
            mx = fmaxf(mx, lrelu(ss[s * H + h] + sdv));
        }
#pragma unroll
        for (int o = 16; o; o >>= 1) mx = fmaxf(mx, __shfl_xor_sync(0xffffffffu, mx, o));
        float sm = 0.f;
        for (int j = lane; j < capped; j += 32) sm += expf(s_e[g][j * H + h] - mx);
        for (int j = CAP + lane; j < deg; j += 32) {
            int s = g_csrc[base + j];
            sm += expf(lrelu(ss[s * H + h] + sdv) - mx);
        }
#pragma unroll
        for (int o = 16; o; o >>= 1) sm += __shfl_xor_sync(0xffffffffu, sm, o);
        if (lane == 0) { s_m[g][h] = mx; s_inv[g][h] = 1.f / (sm + 1e-16f); }
    }
    GBAR();

    {
        const int jj = (H == 1) ? gt : (gt >> 2);
        const int h  = (H == 1) ? 0 : (gt & 3);
        const float mh = s_m[g][h], iv = s_inv[g][h];
        for (int j0 = 0; j0 < capped; j0 += GSZ / H) {
            int j = j0 + jj;
            if (j < capped) s_e[g][j * H + h] = expf(s_e[g][j * H + h] - mh) * iv;
        }
    }
    GBAR();

    const int hh = (gt * PH) / C;   // warp-uniform
    float acc[PH];
#pragma unroll
    for (int k = 0; k < PH; k++) acc[k] = 0.f;
    const float* we = &s_e[g][0];
    const int* sidx = &s_idx[g][0];

    if (PH == 8) {
        const __half* fb = feat + gt * 8;
        uint4 b0 = make_uint4(0, 0, 0, 0), b1 = b0, b2 = b0, b3 = b0;
        if (capped > 0) b0 = *(const uint4*)(fb + (size_t)sidx[0] * HC);
        if (capped > 1) b1 = *(const uint4*)(fb + (size_t)sidx[1] * HC);
        if (capped > 2) b2 = *(const uint4*)(fb + (size_t)sidx[2] * HC);
        if (capped > 3) b3 = *(const uint4*)(fb + (size_t)sidx[3] * HC);
        int j = 0;
        for (; j + 4 <= capped; j += 4) {
            float w0 = we[(j + 0) * H + hh], w1 = we[(j + 1) * H + hh];
            float w2 = we[(j + 2) * H + hh], w3 = we[(j + 3) * H + hh];
            uint4 v0 = b0, v1 = b1, v2 = b2, v3 = b3;
            if (j + 4 < capped) b0 = *(const uint4*)(fb + (size_t)sidx[j + 4] * HC);
            if (j + 5 < capped) b1 = *(const uint4*)(fb + (size_t)sidx[j + 5] * HC);
            if (j + 6 < capped) b2 = *(const uint4*)(fb + (size_t)sidx[j + 6] * HC);
            if (j + 7 < capped) b3 = *(const uint4*)(fb + (size_t)sidx[j + 7] * HC);
            acc8(acc, v0, w0); acc8(acc, v1, w1); acc8(acc, v2, w2); acc8(acc, v3, w3);
        }
        if (j     < capped) acc8(acc, b0, we[(j + 0) * H + hh]);
        if (j + 1 < capped) acc8(acc, b1, we[(j + 1) * H + hh]);
        if (j + 2 < capped) acc8(acc, b2, we[(j + 2) * H + hh]);
    } else {
        const __half* fb = feat + gt * 4;
        uint2 b0 = make_uint2(0, 0), b1 = b0, b2 = b0, b3 = b0;
        if (capped > 0) b0 = *(const uint2*)(fb + (size_t)sidx[0] * HC);
        if (capped > 1) b1 = *(const uint2*)(fb + (size_t)sidx[1] * HC);
        if (capped > 2) b2 = *(const uint2*)(fb + (size_t)sidx[2] * HC);
        if (capped > 3) b3 = *(const uint2*)(fb + (size_t)sidx[3] * HC);
        int j = 0;
        for (; j + 4 <= capped; j += 4) {
            float w0 = we[(j + 0) * H + hh], w1 = we[(j + 1) * H + hh];
            float w2 = we[(j + 2) * H + hh], w3 = we[(j + 3) * H + hh];
            uint2 v0 = b0, v1 = b1, v2 = b2, v3 = b3;
            if (j + 4 < capped) b0 = *(const uint2*)(fb + (size_t)sidx[j + 4] * HC);
            if (j + 5 < capped) b1 = *(const uint2*)(fb + (size_t)sidx[j + 5] * HC);
            if (j + 6 < capped) b2 = *(const uint2*)(fb + (size_t)sidx[j + 6] * HC);
            if (j + 7 < capped) b3 = *(const uint2*)(fb + (size_t)sidx[j + 7] * HC);
            acc4(acc, v0, w0); acc4(acc, v1, w1); acc4(acc, v2, w2); acc4(acc, v3, w3);
        }
        if (j     < capped) acc4(acc, b0, we[(j + 0) * H + hh]);
        if (j + 1 < capped) acc4(acc, b1, we[(j + 1) * H + hh]);
        if (j + 2 < capped) acc4(acc, b2, we[(j + 2) * H + hh]);
    }

    if (deg > CAP) {
        const float mh = s_m[g][hh], iv = s_inv[g][hh];
        const float sdv = sd[d * H + hh];
        for (int j = CAP; j < deg; j++) {
            int s = g_csrc[base + j];
            float w = expf(lrelu(ss[s * H + hh] + sdv) - mh) * iv;
            if (PH == 8) acc8(acc, *(const uint4*)(feat + (size_t)s * HC + gt * 8), w);
            else         acc4(acc, *(const uint2*)(feat + (size_t)s * HC + gt * 4), w);
        }
    }

    const int c0 = gt * PH;
    float vv[PH];
#pragma unroll
    for (int k = 0; k < PH; k++) {
        float v = acc[k] + bias[c0 + k];
        vv[k] = v > 0.f ? v : expm1f(v);
    }
    if (out) {
#pragma unroll
        for (int k = 0; k < PH; k += 2)
            *(float2*)&out[(size_t)d * HC + c0 + k] = make_float2(vv[k], vv[k + 1]);
    }
#pragma unroll
    for (int k = 0; k < PH; k += 2)
        *(__half2*)&oh[(size_t)d * HC + c0 + k] = __floats2half2_rn(vv[k], vv[k + 1]);
#undef GBAR
}

// ---------------- graph mean + sigmoid ----------------
__global__ void k_zero_gf(float* gf) { gf[threadIdx.x] = 0.f; }
__global__ void k_colsum(const float* __restrict__ h, float* __restrict__ gf) {
    float acc = 0.f;
    int t = threadIdx.x;
    for (int r = blockIdx.x; r < NN; r += gridDim.x) acc += h[(size_t)r * F2 + t];
    atomicAdd(&gf[t], acc);
}
__global__ void k_scale_gf(float* gf) { gf[threadIdx.x] *= (1.0f / (float)NN); }

__global__ void k_sigmoid(const float* __restrict__ yp, const float* __restrict__ bp2,
                          float* __restrict__ infl, int n, int i0) {
    int i = blockIdx.x * blockDim.x + threadIdx.x;
    if (i < n) infl[i0 + i] = 1.f / (1.f + expf(-(yp[i0 + i] + bp2[0])));
}

// ---------------- host: tensor-map builder ----------------
typedef CUresult (*PFN_encodeTiled)(
    CUtensorMap*, CUtensorMapDataType, cuuint32_t, void*,
    const cuuint64_t*, const cuuint64_t*, const cuuint32_t*, const cuuint32_t*,
    CUtensorMapInterleave, CUtensorMapSwizzle, CUtensorMapL2promotion,
    CUtensorMapFloatOOBfill);

static CUtensorMap make_map(PFN_encodeTiled enc, void* base, int K, int rows) {
    CUtensorMap m;
    cuuint64_t dims[2]    = {(cuuint64_t)K, (cuuint64_t)rows};
    cuuint64_t strides[1] = {(cuuint64_t)K * 2};
    cuuint32_t box[2]     = {64, 128};
    cuuint32_t es[2]      = {1, 1};
    enc(&m, CU_TENSOR_MAP_DATA_TYPE_FLOAT16, 2, base, dims, strides, box, es,
        CU_TENSOR_MAP_INTERLEAVE_NONE, CU_TENSOR_MAP_SWIZZLE_128B,
        CU_TENSOR_MAP_L2_PROMOTION_L2_128B, CU_TENSOR_MAP_FLOAT_OOB_FILL_NONE);
    return m;
}

// ---------------- launch ----------------
extern "C" void kernel_launch(void* const* d_in, const int* in_sizes, int n_in,
                              void* d_out, int out_size) {
    const float* x   = (const float*)d_in[0];
    const int*   eidx = (const int*)d_in[1];
    const float* W1  = (const float*)d_in[2];
    const float* as1 = (const float*)d_in[3];
    const float* ad1 = (const float*)d_in[4];
    const float* b1  = (const float*)d_in[5];
    const float* W2  = (const float*)d_in[6];
    const float* as2 = (const float*)d_in[7];
    const float* ad2 = (const float*)d_in[8];
    const float* b2  = (const float*)d_in[9];
    const float* Wp1 = (const float*)d_in[10];
    const float* bp1 = (const float*)d_in[11];
    const float* Wp2 = (const float*)d_in[12];
    const float* bp2 = (const float*)d_in[13];

    const int* src = eidx;
    const int* dst = eidx + EE;

    float* out   = (float*)d_out;
    float* out_h = out;
    float* out_g = out + (size_t)NN * F2;
    float* out_i = out_g + F2;

    float *p_yp, *p_ss1, *p_sd1, *p_ss2, *p_sd2;
    int* p_deg;
    __half *p_xh, *p_w1h, *p_h1h, *p_o1h, *p_w2h, *p_h2h, *p_hh, *p_wph;
    cudaGetSymbolAddress((void**)&p_yp, g_yp);
    cudaGetSymbolAddress((void**)&p_ss1, g_ss1);
    cudaGetSymbolAddress((void**)&p_sd1, g_sd1);
    cudaGetSymbolAddress((void**)&p_ss2, g_ss2);
    cudaGetSymbolAddress((void**)&p_sd2, g_sd2);
    cudaGetSymbolAddress((void**)&p_deg, g_deg);
    cudaGetSymbolAddress((void**)&p_xh,  g_xh);
    cudaGetSymbolAddress((void**)&p_w1h, g_w1h);
    cudaGetSymbolAddress((void**)&p_h1h, g_h1h);
    cudaGetSymbolAddress((void**)&p_o1h, g_o1h);
    cudaGetSymbolAddress((void**)&p_w2h, g_w2h);
    cudaGetSymbolAddress((void**)&p_h2h, g_h2h);
    cudaGetSymbolAddress((void**)&p_hh,  g_hh);
    cudaGetSymbolAddress((void**)&p_wph, g_wph);

    PFN_encodeTiled enc = nullptr;
    cudaGetDriverEntryPoint("cuTensorMapEncodeTiled", (void**)&enc, cudaEnableDefault);

    CUtensorMap mA1 = make_map(enc, p_xh,  FIN, NN);
    CUtensorMap mB1 = make_map(enc, p_w1h, FIN, F1);
    CUtensorMap mA2 = make_map(enc, p_o1h, F1,  NN);
    CUtensorMap mB2 = make_map(enc, p_w2h, F1,  F2);
    CUtensorMap mA3 = make_map(enc, p_hh,  F2,  NN);
    CUtensorMap mB3 = make_map(enc, p_wph, F2, PHID);

    cudaFuncSetAttribute(hgemm_tma, cudaFuncAttributeMaxDynamicSharedMemorySize, TG_SMEM);

    static cudaStream_t s1 = nullptr;
    static cudaEvent_t evF1 = nullptr, evZW = nullptr, evJ1 = nullptr, evA1lo = nullptr,
                       evS1a = nullptr, evA2lo = nullptr, evA2hi = nullptr, evJ2 = nullptr;
    if (!s1) {
        cudaStreamCreateWithFlags(&s1, cudaStreamNonBlocking);
        cudaEventCreateWithFlags(&evF1,  cudaEventDisableTiming);
        cudaEventCreateWithFlags(&evZW,  cudaEventDisableTiming);
        cudaEventCreateWithFlags(&evJ1,  cudaEventDisableTiming);
        cudaEventCreateWithFlags(&evA1lo, cudaEventDisableTiming);
        cudaEventCreateWithFlags(&evS1a, cudaEventDisableTiming);
        cudaEventCreateWithFlags(&evA2lo, cudaEventDisableTiming);
        cudaEventCreateWithFlags(&evA2hi, cudaEventDisableTiming);
        cudaEventCreateWithFlags(&evJ2,  cudaEventDisableTiming);
    }

    // ---- fork 1: zeros+deg_init + W1 cast -> evZW, then W2/Wp1 casts + CSR ----
    cudaEventRecord(evF1, 0);
    cudaStreamWaitEvent(s1, evF1, 0);
    k_zeroinit<<<(NN * HH1 + 255) / 256, 256, 0, s1>>>(p_ss1, p_sd1, p_ss2, p_sd2, p_yp,
                                                       p_deg, NN * HH1, NN);
    k_castT2<<<((FIN / 2) * F1 + 255) / 256, 256, 0, s1>>>(W1, p_w1h, FIN, F1);
    cudaEventRecord(evZW, s1);
    k_castT2<<<((F1 / 2) * F2 + 255) / 256, 256, 0, s1>>>(W2, p_w2h, F1, F2);
    k_castT2<<<((F2 / 2) * PHID + 255) / 256, 256, 0, s1>>>(Wp1, p_wph, F2, PHID);
    k_deg_count<<<(EE + 255) / 256, 256, 0, s1>>>(dst, EE);
    k_scan<<<1, 1024, 0, s1>>>(NN);
    k_fill<<<(ETOT + 255) / 256, 256, 0, s1>>>(src, dst, EE, NN);
    cudaEventRecord(evJ1, s1);

    // ---- main: cast x (vectorized) -> GEMM1 (fp16 out + fused ss1/sd1) ----
    k_cast4<<<(NN * FIN / 4 + 255) / 256, 256>>>((const float4*)x, (__half2*)p_xh, NN * FIN / 4);
    cudaStreamWaitEvent(0, evZW, 0);
    hgemm_tma<<<dim3(F1 / 128, TLO + THI), 256, TG_SMEM>>>(mA1, mB1, nullptr, p_h1h,
                                                           NN, F1, FIN, 0,
                                                           p_ss1, p_sd1, as1, ad1,
                                                           nullptr, nullptr, nullptr);
    cudaStreamWaitEvent(0, evJ1, 0);

    // ---- agg1 split-pipeline with GEMM2 (fp16 out + fused ss2/sd2) ----
    k_agg<HH1, HD, 128><<<NSPLIT / 2, 256>>>(p_h1h, p_ss1, p_sd1, b1, nullptr, p_o1h, 0);
    cudaEventRecord(evA1lo, 0);
    cudaStreamWaitEvent(s1, evA1lo, 0);
    hgemm_tma<<<dim3(F2 / 128, TLO), 256, TG_SMEM, s1>>>(mA2, mB2, nullptr, p_h2h,
                                                         NN, F2, F1, 0,
                                                         p_ss2, p_sd2, as2, ad2,
                                                         nullptr, nullptr, nullptr);
    cudaEventRecord(evS1a, s1);

    k_agg<HH1, HD, 128><<<(NN - NSPLIT) / 2, 256>>>(p_h1h, p_ss1, p_sd1, b1, nullptr, p_o1h, NSPLIT);
    hgemm_tma<<<dim3(F2 / 128, THI), 256, TG_SMEM>>>(mA2, mB2, nullptr, p_h2h,
                                                     NN, F2, F1, TLO,
                                                     p_ss2, p_sd2, as2, ad2,
                                                     nullptr, nullptr, nullptr);
    cudaStreamWaitEvent(0, evS1a, 0);

    // ---- agg2 split-pipeline with GEMM3 (fused influence partial) ----
    k_agg<1, F2, 64><<<NSPLIT / 4, 256>>>(p_h2h, p_ss2, p_sd2, b2, out_h, p_hh, 0);
    cudaEventRecord(evA2lo, 0);
    cudaStreamWaitEvent(s1, evA2lo, 0);
    hgemm_tma<<<dim3(1, TLO), 256, TG_SMEM, s1>>>(mA3, mB3, nullptr, nullptr,
                                                  NN, PHID, F2, 0,
                                                  nullptr, nullptr, nullptr, nullptr,
                                                  p_yp, bp1, Wp2);
    k_sigmoid<<<(NSPLIT + 255) / 256, 256, 0, s1>>>(p_yp, bp2, out_i, NSPLIT, 0);

    k_agg<1, F2, 64><<<(NN - NSPLIT) / 4, 256>>>(p_h2h, p_ss2, p_sd2, b2, out_h, p_hh, NSPLIT);
    cudaEventRecord(evA2hi, 0);

    // side: graph mean (needs full out_h)
    cudaStreamWaitEvent(s1, evA2hi, 0);
    k_zero_gf<<<1, F2, 0, s1>>>(out_g);
    k_colsum<<<160, F2, 0, s1>>>(out_h, out_g);
    k_scale_gf<<<1, F2, 0, s1>>>(out_g);
    cudaEventRecord(evJ2, s1);

    // main: GEMM3_hi (fused influence) + sigmoid_hi
    hgemm_tma<<<dim3(1, THI), 256, TG_SMEM>>>(mA3, mB3, nullptr, nullptr,
                                              NN, PHID, F2, TLO,
                                              nullptr, nullptr, nullptr, nullptr,
                                              p_yp, bp1, Wp2);
    k_sigmoid<<<(NN - NSPLIT + 255) / 256, 256>>>(p_yp, bp2, out_i, NN - NSPLIT, NSPLIT);
    cudaStreamWaitEvent(0, evJ2, 0);
}